// round 12
// baseline (speedup 1.0000x reference)
#include <cuda_runtime.h>
#include <math.h>
#include <stdint.h>

#define D_MODEL 256
#define STATE_N 64
#define SEQ_L   8192
#define HALF_L  4096

// Scratch: K_hat[d, L] complex64 (16 MB) as a device global (no runtime alloc).
__device__ float2 g_Khat[D_MODEL * SEQ_L];

// ---------------------------------------------------------------------------
// tf32 mma (operands: raw f32 bits; HW ignores low 13 mantissa bits = trunc)
// ---------------------------------------------------------------------------
__device__ __forceinline__ void mma_tf32(float& d0, float& d1, float& d2, float& d3,
                                         float a0, float a1, float a2, float a3,
                                         float b0, float b1)
{
    asm volatile(
        "mma.sync.aligned.m16n8k8.row.col.f32.tf32.tf32.f32 "
        "{%0,%1,%2,%3}, {%4,%5,%6,%7}, {%8,%9}, {%0,%1,%2,%3};"
        : "+f"(d0), "+f"(d1), "+f"(d2), "+f"(d3)
        : "r"(__float_as_uint(a0)), "r"(__float_as_uint(a1)),
          "r"(__float_as_uint(a2)), "r"(__float_as_uint(a3)),
          "r"(__float_as_uint(b0)), "r"(__float_as_uint(b1)));
}

__device__ __forceinline__ uint32_t tf32_rna(float x) {
    uint32_t u;
    asm("cvt.rna.tf32.f32 %0, %1;" : "=r"(u) : "f"(x));
    return u;
}

// ---------------------------------------------------------------------------
// Woodbury tail from the 8 fast-path sums (g purely imaginary form).
// ---------------------------------------------------------------------------
__device__ __forceinline__ float2 wb_fast(float SA, float SB, float SC, float SD,
                                          float TA, float TB, float TC, float TD,
                                          float pfr, float pfi)
{
    float PRBr = SA + TB, PRBi = SB - TA;
    float BRPr = SA - TB, BRPi = -SB - TA;
    float qr = 1.0f + SC, qi = -TC;
    float BRBr = SD, BRBi = -TD;
    float iq = 1.0f / (qr * qr + qi * qi);
    float numr = BRPr * PRBr - BRPi * PRBi;
    float numi = BRPr * PRBi + BRPi * PRBr;
    float tr = (numr * qr + numi * qi) * iq;
    float ti = (numi * qr - numr * qi) * iq;
    float hr = BRBr - tr, hi = BRBi - ti;
    return make_float2(pfr * hr - pfi * hi, pfr * hi + pfi * hr);
}

// ---------------------------------------------------------------------------
// Kernel 1: Cauchy + Woodbury via tf32 mma.sync.
// R12: lambda-data preloaded to registers, split MMA accumulator chains,
// deferred full-warp Woodbury epilogue in padded smem.
// ---------------------------------------------------------------------------
__global__ void __launch_bounds__(256) cauchy_mma(
    const float* __restrict__ Lam_re, const float* __restrict__ Lam_im,
    const float* __restrict__ P_re,   const float* __restrict__ P_im,
    const float* __restrict__ B_re,   const float* __restrict__ B_im,
    const float* __restrict__ log_dt)
{
    __shared__ float2 s_lisp[STATE_N];      // (lam_im, sp*sp)
    __shared__ float  s_Sw[4 * STATE_N];    // tf32-rna S-weights [j][n]
    __shared__ float  s_Tw[4 * STATE_N];    // tf32-rna T-weights [j][n]
    __shared__ float  s_gi[1024], s_pfr[1024], s_pfi[1024];
    __shared__ float  s_sums[8][8][132];    // [warp][sum-col][kloc padded]
    __shared__ float  s_scal_sh;

    const int d    = blockIdx.y;
    const int seg  = blockIdx.x;
    const int tid  = threadIdx.x;
    const int lane = tid & 31;
    const int warp = tid >> 5;

    if (tid < STATE_N) {
        const int idx = d * STATE_N + tid;
        float lr = Lam_re[idx];
        float li = Lam_im[idx];
        float sp = fmaxf(lr, 0.0f) + log1pf(expf(-fabsf(lr)));  // softplus
        float pr = P_re[idx], pi = P_im[idx];
        float br = B_re[idx], bi = B_im[idx];
        float w1r = pr * br + pi * bi;    // conj(P)*B
        float w1i = pr * bi - pi * br;
        float pp  = pr * pr + pi * pi;
        float bb  = br * br + bi * bi;
        s_lisp[tid] = make_float2(li, sp * sp);
        s_Sw[0 * STATE_N + tid] = __uint_as_float(tf32_rna(w1r * sp));
        s_Sw[1 * STATE_N + tid] = __uint_as_float(tf32_rna(w1i * sp));
        s_Sw[2 * STATE_N + tid] = __uint_as_float(tf32_rna(pp * sp));
        s_Sw[3 * STATE_N + tid] = __uint_as_float(tf32_rna(bb * sp));
        s_Tw[0 * STATE_N + tid] = __uint_as_float(tf32_rna(w1r));
        s_Tw[1 * STATE_N + tid] = __uint_as_float(tf32_rna(w1i));
        s_Tw[2 * STATE_N + tid] = __uint_as_float(tf32_rna(pp));
        s_Tw[3 * STATE_N + tid] = __uint_as_float(tf32_rna(bb));
    }
    if (tid == 0) s_scal_sh = 2.0f * expf(-log_dt[d]);
    __syncthreads();

    // per-k prologue: gi, pref (f32 arithmetic matching the reference)
    const float scal = s_scal_sh;
    const float w0 = (float)(-6.283185307179586476925286766559 / (double)SEQ_L);
    for (int kk = tid; kk < 1024; kk += 256) {
        int k = seg * 1024 + kk;
        float zs, zc;
        sincosf(w0 * (float)k, &zs, &zc);
        float dzr = 1.0f + zc, dzi = zs;
        if (k == HALF_L) { dzr = 1.1920929e-7f; dzi = 0.0f; }
        float idm = 1.0f / (dzr * dzr + dzi * dzi);
        float nr = 1.0f - zc, ni = -zs;
        s_gi[kk]  = scal * (ni * dzr - nr * dzi) * idm;
        s_pfr[kk] = 2.0f * dzr * idm;
        s_pfi[kk] = -2.0f * dzi * idm;
    }
    __syncthreads();

    const int j  = lane >> 2;       // B-fragment n-column 0..7
    const int qr = lane & 3;

    // Preload B fragments (constant over all tiles).
    float pS0[8], pS1[8], pT0[8], pT1[8];
#pragma unroll
    for (int ch = 0; ch < 8; ch++) {
        int n0 = ch * 8 + qr, n1 = n0 + 4;
        if (j < 4) {
            pS0[ch] = s_Sw[j * STATE_N + n0];
            pS1[ch] = s_Sw[j * STATE_N + n1];
            pT0[ch] = 0.f; pT1[ch] = 0.f;
        } else {
            pS0[ch] = 0.f; pS1[ch] = 0.f;
            pT0[ch] = s_Tw[(j - 4) * STATE_N + n0];
            pT1[ch] = s_Tw[(j - 4) * STATE_N + n1];
        }
    }
    // Preload lambda data for this lane's A-fragment k-slots.
    float2 plA[8], plB[8];
#pragma unroll
    for (int ch = 0; ch < 8; ch++) {
        plA[ch] = s_lisp[ch * 8 + qr];
        plB[ch] = s_lisp[ch * 8 + qr + 4];
    }

    float* swp = &s_sums[warp][0][0];

    for (int t = 0; t < 8; t++) {
        const int base = (warp * 8 + t) * 16;
        const float gi0 = s_gi[base + (lane >> 2)];       // row l/4
        const float gi1 = s_gi[base + 8 + (lane >> 2)];   // row 8 + l/4

        float dS0 = 0.f, dS1 = 0.f, dS2 = 0.f, dS3 = 0.f;
        float dT0 = 0.f, dT1 = 0.f, dT2 = 0.f, dT3 = 0.f;

#pragma unroll
        for (int ch = 0; ch < 8; ch++) {
            float2 cA = plA[ch];
            float2 cB = plB[ch];

            float di0 = gi0 - cA.x;
            float di1 = gi1 - cA.x;
            float di2 = gi0 - cB.x;
            float di3 = gi1 - cB.x;
            float m0 = fmaf(di0, di0, cA.y);
            float m1 = fmaf(di1, di1, cA.y);
            float m2 = fmaf(di2, di2, cB.y);
            float m3 = fmaf(di3, di3, cB.y);
            float p01, p23;
            float q01 = m0 * m1, q23 = m2 * m3;
            asm("rcp.approx.f32 %0, %1;" : "=f"(p01) : "f"(q01));
            asm("rcp.approx.f32 %0, %1;" : "=f"(p23) : "f"(q23));
            float i0 = p01 * m1, i1 = p01 * m0;
            float i2 = p23 * m3, i3 = p23 * m2;
            float r0 = di0 * i0, r1 = di1 * i1;
            float r2 = di2 * i2, r3 = di3 * i3;

            mma_tf32(dS0, dS1, dS2, dS3, i0, i1, i2, i3, pS0[ch], pS1[ch]);
            mma_tf32(dT0, dT1, dT2, dT3, r0, r1, r2, r3, pT0[ch], pT1[ch]);
        }

        float d0 = dS0 + dT0, d1 = dS1 + dT1;
        float d2 = dS2 + dT2, d3 = dS3 + dT3;

        // stage D: layout [col][kloc] (padded 132); conflict-free.
        int kl0 = t * 16 + (lane >> 2);
        swp[(2 * qr)     * 132 + kl0]     = d0;
        swp[(2 * qr + 1) * 132 + kl0]     = d1;
        swp[(2 * qr)     * 132 + kl0 + 8] = d2;
        swp[(2 * qr + 1) * 132 + kl0 + 8] = d3;
    }

    __syncwarp();

    // Deferred full-warp Woodbury: 4 k-points per lane.
#pragma unroll
    for (int tt = 0; tt < 4; tt++) {
        int kloc = tt * 32 + lane;
        float SA = swp[0 * 132 + kloc];
        float SB = swp[1 * 132 + kloc];
        float SC = swp[2 * 132 + kloc];
        float SD = swp[3 * 132 + kloc];
        float TA = swp[4 * 132 + kloc];
        float TB = swp[5 * 132 + kloc];
        float TC = swp[6 * 132 + kloc];
        float TD = swp[7 * 132 + kloc];
        int kk = warp * 128 + kloc;
        float2 r = wb_fast(SA, SB, SC, SD, TA, TB, TC, TD,
                           s_pfr[kk], s_pfi[kk]);
        g_Khat[d * SEQ_L + seg * 1024 + kk] = r;
    }

    // ---- exact fix of the eps-clamped point k = L/2 (tid 0 of seg 4 wrote
    // it above; same thread overwrites in program order) ----
    if (seg == 4 && tid == 0) {
        float zs, zc;
        sincosf(w0 * (float)HALF_L, &zs, &zc);
        float dzr = 1.1920929e-7f, dzi = 0.0f;
        float idm = 1.0f / (dzr * dzr + dzi * dzi);
        float nr = 1.0f - zc, ni = -zs;
        float gr = scal * (nr * dzr + ni * dzi) * idm;
        float gi = scal * (ni * dzr - nr * dzi) * idm;
        float pfr = 2.0f * dzr * idm, pfi = -2.0f * dzi * idm;

        float PRBr=0,PRBi=0,BRPr=0,BRPi=0,PRPr=0,PRPi=0,BRBr=0,BRBi=0;
        for (int n = 0; n < STATE_N; n++) {
            const int idx = d * STATE_N + n;
            float lr = Lam_re[idx];
            float li = Lam_im[idx];
            float sp = fmaxf(lr, 0.0f) + log1pf(expf(-fabsf(lr)));
            float pr = P_re[idx], pi = P_im[idx];
            float br = B_re[idx], bi = B_im[idx];
            float w1r = pr * br + pi * bi;
            float w1i = pr * bi - pi * br;
            float pp  = pr * pr + pi * pi;
            float bb  = br * br + bi * bi;
            float dr = gr + sp;
            float di = gi - li;
            float m  = fmaf(dr, dr, di * di);
            float inv = 1.0f / m;
            float Rtr = dr * inv;
            float Rti = -di * inv;
            PRBr += w1r * Rtr - w1i * Rti;
            PRBi += w1r * Rti + w1i * Rtr;
            BRPr += w1r * Rtr + w1i * Rti;
            BRPi += w1r * Rti - w1i * Rtr;
            PRPr += pp * Rtr;  PRPi += pp * Rti;
            BRBr += bb * Rtr;  BRBi += bb * Rti;
        }
        float qr2 = 1.0f + PRPr, qi2 = PRPi;
        float iq = 1.0f / (qr2 * qr2 + qi2 * qi2);
        float numr = BRPr * PRBr - BRPi * PRBi;
        float numi = BRPr * PRBi + BRPi * PRBr;
        float tr = (numr * qr2 + numi * qi2) * iq;
        float ti = (numi * qr2 - numr * qi2) * iq;
        float hr = BRBr - tr, hi = BRBi - ti;
        g_Khat[d * SEQ_L + HALF_L] = make_float2(pfr * hr - pfi * hi,
                                                 pfr * hi + pfi * hr);
    }
}

// ---------------------------------------------------------------------------
// Profiling positioner (keeps cauchy in ncu's captured slot = launch #4).
// ---------------------------------------------------------------------------
__global__ void dummy_a() {}

// ---------------------------------------------------------------------------
// Kernel 2: Re(ifft_L(X)) = Hermitian fold + 4096-pt radix-4 inverse Stockham.
// One CTA per d-row, 64 KB smem ping-pong, 1024 threads.
// ---------------------------------------------------------------------------
__global__ void __launch_bounds__(1024) ifft_kernel(float* __restrict__ out)
{
    extern __shared__ float2 sm[];
    float2* x = sm;
    float2* y = sm + HALF_L;

    const int d   = blockIdx.x;
    const int tid = threadIdx.x;
    const int NT  = 1024;

    const float2* src = g_Khat + d * SEQ_L;

    // Hermitian fold + even/odd pack:  x[k] = E[k] + i*O[k]
    const float thL = 6.28318530717958647692f / (float)SEQ_L;
    for (int kk = tid; kk < HALF_L; kk += NT) {
        float2 Xa  = src[kk];
        float2 Xam = src[kk == 0 ? 0 : SEQ_L - kk];
        float2 Xb  = src[kk + HALF_L];
        float2 Xbm = src[HALF_L - kk];
        float Ar = 0.5f * (Xa.x + Xam.x), Ai = 0.5f * (Xa.y - Xam.y);
        float Br = 0.5f * (Xb.x + Xbm.x), Bi = 0.5f * (Xb.y - Xbm.y);
        float Er = 0.5f * (Ar + Br), Ei = 0.5f * (Ai + Bi);
        float Dr = 0.5f * (Ar - Br), Di = 0.5f * (Ai - Bi);
        float swr, swi;
        __sincosf(thL * (float)kk, &swi, &swr);
        float Or = Dr * swr - Di * swi;
        float Oi = Dr * swi + Di * swr;
        x[kk] = make_float2(Er - Oi, Ei + Or);
    }
    __syncthreads();

    int n = HALF_L, s = 1, ls = 0;
    while (n > 1) {
        const int m = n >> 2;
        const float th = 6.28318530717958647692f / (float)n;
        for (int u = tid; u < (HALF_L >> 2); u += NT) {
            int p = u >> ls;
            int q = u & (s - 1);
            int base = q + s * p;
            float2 a  = x[base];
            float2 b  = x[base + s * m];
            float2 c  = x[base + s * 2 * m];
            float2 dd = x[base + s * 3 * m];

            float w1i, w1r;
            __sincosf(th * (float)p, &w1i, &w1r);
            float w2r = w1r * w1r - w1i * w1i;
            float w2i = 2.0f * w1r * w1i;
            float w3r = w2r * w1r - w2i * w1i;
            float w3i = w2r * w1i + w2i * w1r;

            float acr = a.x + c.x, aci = a.y + c.y;
            float amr = a.x - c.x, ami = a.y - c.y;
            float bdr = b.x + dd.x, bdi = b.y + dd.y;
            float bmr = b.x - dd.x, bmi = b.y - dd.y;

            float X0r = acr + bdr, X0i = aci + bdi;
            float X2r = acr - bdr, X2i = aci - bdi;
            float X1r = amr - bmi, X1i = ami + bmr;
            float X3r = amr + bmi, X3i = ami - bmr;

            int ob = q + s * 4 * p;
            y[ob]         = make_float2(X0r, X0i);
            y[ob + s]     = make_float2(X1r * w1r - X1i * w1i,
                                        X1r * w1i + X1i * w1r);
            y[ob + 2 * s] = make_float2(X2r * w2r - X2i * w2i,
                                        X2r * w2i + X2i * w2r);
            y[ob + 3 * s] = make_float2(X3r * w3r - X3i * w3i,
                                        X3r * w3i + X3i * w3r);
        }
        __syncthreads();
        float2* tmp = x; x = y; y = tmp;
        n = m; s <<= 2; ls += 2;
    }

    const float scale = 1.0f / (float)HALF_L;
    float* dstp = out + d * SEQ_L;
    for (int mI = tid; mI < HALF_L; mI += NT) {
        float2 v = x[mI];
        dstp[2 * mI]     = v.x * scale;
        dstp[2 * mI + 1] = v.y * scale;
    }
}

// ---------------------------------------------------------------------------
extern "C" void kernel_launch(void* const* d_in, const int* in_sizes, int n_in,
                              void* d_out, int out_size)
{
    const float* Lam_re = (const float*)d_in[0];
    const float* Lam_im = (const float*)d_in[1];
    const float* P_re   = (const float*)d_in[2];
    const float* P_im   = (const float*)d_in[3];
    const float* B_re   = (const float*)d_in[4];
    const float* B_im   = (const float*)d_in[5];
    const float* log_dt = (const float*)d_in[6];

    float* out = (float*)d_out;

    // Stage 1: Cauchy + Woodbury via tf32 MMA (incl. exact k=L/2 fix)
    dim3 gridA(SEQ_L / 1024, D_MODEL);   // 8 x 256
    cauchy_mma<<<gridA, 256>>>(Lam_re, Lam_im, P_re, P_im, B_re, B_im, log_dt);

    // Stage 2: Hermitian fold + radix-4 half-length iFFT per row -> K
    cudaFuncSetAttribute(ifft_kernel,
                         cudaFuncAttributeMaxDynamicSharedMemorySize, 65536);
    ifft_kernel<<<D_MODEL, 1024, 65536>>>(out);

    // keep cauchy in the ncu capture slot (#4 overall)
    dummy_a<<<1, 32>>>();

    // Tail of the output: D buffer (zeros in the reference)
    long kElems = (long)D_MODEL * SEQ_L;
    if ((long)out_size > kElems) {
        cudaMemsetAsync(out + kElems, 0,
                        ((long)out_size - kElems) * sizeof(float), 0);
    }
}

// round 13
// speedup vs baseline: 1.0249x; 1.0249x over previous
#include <cuda_runtime.h>
#include <math.h>
#include <stdint.h>

#define D_MODEL 256
#define STATE_N 64
#define SEQ_L   8192
#define HALF_L  4096

// Scratch: K_hat[d, L] complex64 (16 MB) as a device global (no runtime alloc).
__device__ float2 g_Khat[D_MODEL * SEQ_L];

// ---------------------------------------------------------------------------
// tf32 mma (operands: raw f32 bits; HW ignores low 13 mantissa bits = trunc)
// ---------------------------------------------------------------------------
__device__ __forceinline__ void mma_tf32(float& d0, float& d1, float& d2, float& d3,
                                         float a0, float a1, float a2, float a3,
                                         float b0, float b1)
{
    asm volatile(
        "mma.sync.aligned.m16n8k8.row.col.f32.tf32.tf32.f32 "
        "{%0,%1,%2,%3}, {%4,%5,%6,%7}, {%8,%9}, {%0,%1,%2,%3};"
        : "+f"(d0), "+f"(d1), "+f"(d2), "+f"(d3)
        : "r"(__float_as_uint(a0)), "r"(__float_as_uint(a1)),
          "r"(__float_as_uint(a2)), "r"(__float_as_uint(a3)),
          "r"(__float_as_uint(b0)), "r"(__float_as_uint(b1)));
}

__device__ __forceinline__ uint32_t tf32_rna(float x) {
    uint32_t u;
    asm("cvt.rna.tf32.f32 %0, %1;" : "=r"(u) : "f"(x));
    return u;
}

// ---------------------------------------------------------------------------
// Woodbury tail from the 8 fast-path sums (g purely imaginary form).
// ---------------------------------------------------------------------------
__device__ __forceinline__ float2 wb_fast(float SA, float SB, float SC, float SD,
                                          float TA, float TB, float TC, float TD,
                                          float pfr, float pfi)
{
    float PRBr = SA + TB, PRBi = SB - TA;
    float BRPr = SA - TB, BRPi = -SB - TA;
    float qr = 1.0f + SC, qi = -TC;
    float BRBr = SD, BRBi = -TD;
    float iq = 1.0f / (qr * qr + qi * qi);
    float numr = BRPr * PRBr - BRPi * PRBi;
    float numi = BRPr * PRBi + BRPi * PRBr;
    float tr = (numr * qr + numi * qi) * iq;
    float ti = (numi * qr - numr * qi) * iq;
    float hr = BRBr - tr, hi = BRBi - ti;
    return make_float2(pfr * hr - pfi * hi, pfr * hi + pfi * hr);
}

// ---------------------------------------------------------------------------
// Kernel 1: Cauchy + Woodbury via tf32 mma.sync.
// R13: per-chunk constants as packed float4 shared loads (2 x LDS.128/chunk),
// occupancy pinned at 5 CTAs/SM to stop register re-hoisting.
// ---------------------------------------------------------------------------
__global__ void __launch_bounds__(256, 5) cauchy_mma(
    const float* __restrict__ Lam_re, const float* __restrict__ Lam_im,
    const float* __restrict__ P_re,   const float* __restrict__ P_im,
    const float* __restrict__ B_re,   const float* __restrict__ B_im,
    const float* __restrict__ log_dt)
{
    __shared__ float2 s_lisp[STATE_N];       // (lam_im, sp*sp) [init temp]
    __shared__ float  s_Sw[4 * STATE_N];     // tf32-rna S-weights [init temp]
    __shared__ float  s_Tw[4 * STATE_N];     // tf32-rna T-weights [init temp]
    __shared__ float4 s_lam4[32];            // [ch*4+qr] = (liA, sp2A, liB, sp2B)
    __shared__ float4 s_bf4[256];            // [(j*8+ch)*4+qr] = (S0,S1,T0,T1)
    __shared__ float  s_gi[1024], s_pfr[1024], s_pfi[1024];
    __shared__ float  s_sums[8][16][8];      // per-warp D staging
    __shared__ float  s_scal_sh;

    const int d    = blockIdx.y;
    const int seg  = blockIdx.x;
    const int tid  = threadIdx.x;
    const int lane = tid & 31;
    const int warp = tid >> 5;

    if (tid < STATE_N) {
        const int idx = d * STATE_N + tid;
        float lr = Lam_re[idx];
        float li = Lam_im[idx];
        float sp = fmaxf(lr, 0.0f) + log1pf(expf(-fabsf(lr)));  // softplus
        float pr = P_re[idx], pi = P_im[idx];
        float br = B_re[idx], bi = B_im[idx];
        float w1r = pr * br + pi * bi;    // conj(P)*B
        float w1i = pr * bi - pi * br;
        float pp  = pr * pr + pi * pi;
        float bb  = br * br + bi * bi;
        s_lisp[tid] = make_float2(li, sp * sp);
        s_Sw[0 * STATE_N + tid] = __uint_as_float(tf32_rna(w1r * sp));
        s_Sw[1 * STATE_N + tid] = __uint_as_float(tf32_rna(w1i * sp));
        s_Sw[2 * STATE_N + tid] = __uint_as_float(tf32_rna(pp * sp));
        s_Sw[3 * STATE_N + tid] = __uint_as_float(tf32_rna(bb * sp));
        s_Tw[0 * STATE_N + tid] = __uint_as_float(tf32_rna(w1r));
        s_Tw[1 * STATE_N + tid] = __uint_as_float(tf32_rna(w1i));
        s_Tw[2 * STATE_N + tid] = __uint_as_float(tf32_rna(pp));
        s_Tw[3 * STATE_N + tid] = __uint_as_float(tf32_rna(bb));
    }
    if (tid == 0) s_scal_sh = 2.0f * expf(-log_dt[d]);
    __syncthreads();

    // Pack per-chunk constants into float4 tables.
    if (tid < 32) {
        int ch = tid >> 2, q = tid & 3;
        int n0 = ch * 8 + q, n1 = n0 + 4;
        float2 a = s_lisp[n0];
        float2 b = s_lisp[n1];
        s_lam4[tid] = make_float4(a.x, a.y, b.x, b.y);
    }
    {
        int t = tid;                      // 256 entries: j(8) x ch(8) x qr(4)
        int jj = t >> 5, ch = (t >> 2) & 7, q = t & 3;
        int n0 = ch * 8 + q, n1 = n0 + 4;
        float4 v;
        if (jj < 4) v = make_float4(s_Sw[jj * STATE_N + n0],
                                    s_Sw[jj * STATE_N + n1], 0.f, 0.f);
        else        v = make_float4(0.f, 0.f,
                                    s_Tw[(jj - 4) * STATE_N + n0],
                                    s_Tw[(jj - 4) * STATE_N + n1]);
        s_bf4[t] = v;
    }

    // per-k prologue: gi, pref (f32 arithmetic matching the reference)
    const float scal = s_scal_sh;
    const float w0 = (float)(-6.283185307179586476925286766559 / (double)SEQ_L);
    for (int kk = tid; kk < 1024; kk += 256) {
        int k = seg * 1024 + kk;
        float zs, zc;
        sincosf(w0 * (float)k, &zs, &zc);
        float dzr = 1.0f + zc, dzi = zs;
        if (k == HALF_L) { dzr = 1.1920929e-7f; dzi = 0.0f; }
        float idm = 1.0f / (dzr * dzr + dzi * dzi);
        float nr = 1.0f - zc, ni = -zs;
        s_gi[kk]  = scal * (ni * dzr - nr * dzi) * idm;
        s_pfr[kk] = 2.0f * dzr * idm;
        s_pfi[kk] = -2.0f * dzi * idm;
    }
    __syncthreads();

    const int j  = lane >> 2;       // B-fragment column 0..7
    const int qr = lane & 3;

    for (int t = 0; t < 8; t++) {
        const int base = (warp * 8 + t) * 16;
        const float gi0 = s_gi[base + (lane >> 2)];       // row l/4
        const float gi1 = s_gi[base + 8 + (lane >> 2)];   // row 8 + l/4

        float dS0 = 0.f, dS1 = 0.f, dS2 = 0.f, dS3 = 0.f;
        float dT0 = 0.f, dT1 = 0.f, dT2 = 0.f, dT3 = 0.f;

#pragma unroll
        for (int ch = 0; ch < 8; ch++) {
            float4 lam = s_lam4[ch * 4 + qr];
            float4 bf  = s_bf4[(j * 8 + ch) * 4 + qr];

            float di0 = gi0 - lam.x;
            float di1 = gi1 - lam.x;
            float di2 = gi0 - lam.z;
            float di3 = gi1 - lam.z;
            float m0 = fmaf(di0, di0, lam.y);
            float m1 = fmaf(di1, di1, lam.y);
            float m2 = fmaf(di2, di2, lam.w);
            float m3 = fmaf(di3, di3, lam.w);
            float p01, p23;
            float q01 = m0 * m1, q23 = m2 * m3;
            asm("rcp.approx.f32 %0, %1;" : "=f"(p01) : "f"(q01));
            asm("rcp.approx.f32 %0, %1;" : "=f"(p23) : "f"(q23));
            float i0 = p01 * m1, i1 = p01 * m0;
            float i2 = p23 * m3, i3 = p23 * m2;
            float r0 = di0 * i0, r1 = di1 * i1;
            float r2 = di2 * i2, r3 = di3 * i3;

            mma_tf32(dS0, dS1, dS2, dS3, i0, i1, i2, i3, bf.x, bf.y);
            mma_tf32(dT0, dT1, dT2, dT3, r0, r1, r2, r3, bf.z, bf.w);
        }

        float d0 = dS0 + dT0, d1 = dS1 + dT1;
        float d2 = dS2 + dT2, d3 = dS3 + dT3;

        // epilogue: stage D to smem, lanes 0..15 run Woodbury for 16 k's
        float (*sw)[8] = s_sums[warp];
        sw[lane >> 2][2 * qr]           = d0;
        sw[lane >> 2][2 * qr + 1]       = d1;
        sw[8 + (lane >> 2)][2 * qr]     = d2;
        sw[8 + (lane >> 2)][2 * qr + 1] = d3;
        __syncwarp();
        if (lane < 16) {
            float SA = sw[lane][0], SB = sw[lane][1];
            float SC = sw[lane][2], SD = sw[lane][3];
            float TA = sw[lane][4], TB = sw[lane][5];
            float TC = sw[lane][6], TD = sw[lane][7];
            int kk = base + lane;
            float2 r = wb_fast(SA, SB, SC, SD, TA, TB, TC, TD,
                               s_pfr[kk], s_pfi[kk]);
            g_Khat[d * SEQ_L + seg * 1024 + kk] = r;
        }
        __syncwarp();
    }

    // ---- exact fix of the eps-clamped point k = L/2 (tid 0 of seg 4 wrote
    // it above; same thread overwrites in program order) ----
    if (seg == 4 && tid == 0) {
        float zs, zc;
        sincosf(w0 * (float)HALF_L, &zs, &zc);
        float dzr = 1.1920929e-7f, dzi = 0.0f;
        float idm = 1.0f / (dzr * dzr + dzi * dzi);
        float nr = 1.0f - zc, ni = -zs;
        float gr = scal * (nr * dzr + ni * dzi) * idm;
        float gi = scal * (ni * dzr - nr * dzi) * idm;
        float pfr = 2.0f * dzr * idm, pfi = -2.0f * dzi * idm;

        float PRBr=0,PRBi=0,BRPr=0,BRPi=0,PRPr=0,PRPi=0,BRBr=0,BRBi=0;
        for (int n = 0; n < STATE_N; n++) {
            const int idx = d * STATE_N + n;
            float lr = Lam_re[idx];
            float li = Lam_im[idx];
            float sp = fmaxf(lr, 0.0f) + log1pf(expf(-fabsf(lr)));
            float pr = P_re[idx], pi = P_im[idx];
            float br = B_re[idx], bi = B_im[idx];
            float w1r = pr * br + pi * bi;
            float w1i = pr * bi - pi * br;
            float pp  = pr * pr + pi * pi;
            float bb  = br * br + bi * bi;
            float dr = gr + sp;
            float di = gi - li;
            float m  = fmaf(dr, dr, di * di);
            float inv = 1.0f / m;
            float Rtr = dr * inv;
            float Rti = -di * inv;
            PRBr += w1r * Rtr - w1i * Rti;
            PRBi += w1r * Rti + w1i * Rtr;
            BRPr += w1r * Rtr + w1i * Rti;
            BRPi += w1r * Rti - w1i * Rtr;
            PRPr += pp * Rtr;  PRPi += pp * Rti;
            BRBr += bb * Rtr;  BRBi += bb * Rti;
        }
        float qr2 = 1.0f + PRPr, qi2 = PRPi;
        float iq = 1.0f / (qr2 * qr2 + qi2 * qi2);
        float numr = BRPr * PRBr - BRPi * PRBi;
        float numi = BRPr * PRBi + BRPi * PRBr;
        float tr = (numr * qr2 + numi * qi2) * iq;
        float ti = (numi * qr2 - numr * qi2) * iq;
        float hr = BRBr - tr, hi = BRBi - ti;
        g_Khat[d * SEQ_L + HALF_L] = make_float2(pfr * hr - pfi * hi,
                                                 pfr * hi + pfi * hr);
    }
}

// ---------------------------------------------------------------------------
// Profiling positioner (keeps cauchy in ncu's captured slot = launch #4).
// ---------------------------------------------------------------------------
__global__ void dummy_a() {}

// ---------------------------------------------------------------------------
// Kernel 2: Re(ifft_L(X)) = Hermitian fold + 4096-pt radix-4 inverse Stockham.
// One CTA per d-row, 64 KB smem ping-pong, 1024 threads.
// ---------------------------------------------------------------------------
__global__ void __launch_bounds__(1024) ifft_kernel(float* __restrict__ out)
{
    extern __shared__ float2 sm[];
    float2* x = sm;
    float2* y = sm + HALF_L;

    const int d   = blockIdx.x;
    const int tid = threadIdx.x;
    const int NT  = 1024;

    const float2* src = g_Khat + d * SEQ_L;

    // Hermitian fold + even/odd pack:  x[k] = E[k] + i*O[k]
    const float thL = 6.28318530717958647692f / (float)SEQ_L;
    for (int kk = tid; kk < HALF_L; kk += NT) {
        float2 Xa  = src[kk];
        float2 Xam = src[kk == 0 ? 0 : SEQ_L - kk];
        float2 Xb  = src[kk + HALF_L];
        float2 Xbm = src[HALF_L - kk];
        float Ar = 0.5f * (Xa.x + Xam.x), Ai = 0.5f * (Xa.y - Xam.y);
        float Br = 0.5f * (Xb.x + Xbm.x), Bi = 0.5f * (Xb.y - Xbm.y);
        float Er = 0.5f * (Ar + Br), Ei = 0.5f * (Ai + Bi);
        float Dr = 0.5f * (Ar - Br), Di = 0.5f * (Ai - Bi);
        float swr, swi;
        __sincosf(thL * (float)kk, &swi, &swr);
        float Or = Dr * swr - Di * swi;
        float Oi = Dr * swi + Di * swr;
        x[kk] = make_float2(Er - Oi, Ei + Or);
    }
    __syncthreads();

    int n = HALF_L, s = 1, ls = 0;
    while (n > 1) {
        const int m = n >> 2;
        const float th = 6.28318530717958647692f / (float)n;
        for (int u = tid; u < (HALF_L >> 2); u += NT) {
            int p = u >> ls;
            int q = u & (s - 1);
            int base = q + s * p;
            float2 a  = x[base];
            float2 b  = x[base + s * m];
            float2 c  = x[base + s * 2 * m];
            float2 dd = x[base + s * 3 * m];

            float w1i, w1r;
            __sincosf(th * (float)p, &w1i, &w1r);
            float w2r = w1r * w1r - w1i * w1i;
            float w2i = 2.0f * w1r * w1i;
            float w3r = w2r * w1r - w2i * w1i;
            float w3i = w2r * w1i + w2i * w1r;

            float acr = a.x + c.x, aci = a.y + c.y;
            float amr = a.x - c.x, ami = a.y - c.y;
            float bdr = b.x + dd.x, bdi = b.y + dd.y;
            float bmr = b.x - dd.x, bmi = b.y - dd.y;

            float X0r = acr + bdr, X0i = aci + bdi;
            float X2r = acr - bdr, X2i = aci - bdi;
            float X1r = amr - bmi, X1i = ami + bmr;
            float X3r = amr + bmi, X3i = ami - bmr;

            int ob = q + s * 4 * p;
            y[ob]         = make_float2(X0r, X0i);
            y[ob + s]     = make_float2(X1r * w1r - X1i * w1i,
                                        X1r * w1i + X1i * w1r);
            y[ob + 2 * s] = make_float2(X2r * w2r - X2i * w2i,
                                        X2r * w2i + X2i * w2r);
            y[ob + 3 * s] = make_float2(X3r * w3r - X3i * w3i,
                                        X3r * w3i + X3i * w3r);
        }
        __syncthreads();
        float2* tmp = x; x = y; y = tmp;
        n = m; s <<= 2; ls += 2;
    }

    const float scale = 1.0f / (float)HALF_L;
    float* dstp = out + d * SEQ_L;
    for (int mI = tid; mI < HALF_L; mI += NT) {
        float2 v = x[mI];
        dstp[2 * mI]     = v.x * scale;
        dstp[2 * mI + 1] = v.y * scale;
    }
}

// ---------------------------------------------------------------------------
extern "C" void kernel_launch(void* const* d_in, const int* in_sizes, int n_in,
                              void* d_out, int out_size)
{
    const float* Lam_re = (const float*)d_in[0];
    const float* Lam_im = (const float*)d_in[1];
    const float* P_re   = (const float*)d_in[2];
    const float* P_im   = (const float*)d_in[3];
    const float* B_re   = (const float*)d_in[4];
    const float* B_im   = (const float*)d_in[5];
    const float* log_dt = (const float*)d_in[6];

    float* out = (float*)d_out;

    // Stage 1: Cauchy + Woodbury via tf32 MMA (incl. exact k=L/2 fix)
    dim3 gridA(SEQ_L / 1024, D_MODEL);   // 8 x 256
    cauchy_mma<<<gridA, 256>>>(Lam_re, Lam_im, P_re, P_im, B_re, B_im, log_dt);

    // Stage 2: Hermitian fold + radix-4 half-length iFFT per row -> K
    cudaFuncSetAttribute(ifft_kernel,
                         cudaFuncAttributeMaxDynamicSharedMemorySize, 65536);
    ifft_kernel<<<D_MODEL, 1024, 65536>>>(out);

    // keep cauchy in the ncu capture slot (#4 overall)
    dummy_a<<<1, 32>>>();

    // Tail of the output: D buffer (zeros in the reference)
    long kElems = (long)D_MODEL * SEQ_L;
    if ((long)out_size > kElems) {
        cudaMemsetAsync(out + kElems, 0,
                        ((long)out_size - kElems) * sizeof(float), 0);
    }
}

// round 14
// speedup vs baseline: 1.0770x; 1.0509x over previous
#include <cuda_runtime.h>
#include <math.h>
#include <stdint.h>

#define D_MODEL 256
#define STATE_N 64
#define SEQ_L   8192
#define HALF_L  4096

// Scratch: K_hat[d, L] complex64 (16 MB) + geometry table (d-independent).
__device__ float2 g_Khat[D_MODEL * SEQ_L];
__device__ float4 g_geom[SEQ_L];   // (tanv, pfr, pfi, 0)

// ---------------------------------------------------------------------------
// tf32 mma (operands: raw f32 bits; HW ignores low 13 mantissa bits = trunc)
// ---------------------------------------------------------------------------
__device__ __forceinline__ void mma_tf32(float& d0, float& d1, float& d2, float& d3,
                                         float a0, float a1, float a2, float a3,
                                         float b0, float b1)
{
    asm volatile(
        "mma.sync.aligned.m16n8k8.row.col.f32.tf32.tf32.f32 "
        "{%0,%1,%2,%3}, {%4,%5,%6,%7}, {%8,%9}, {%0,%1,%2,%3};"
        : "+f"(d0), "+f"(d1), "+f"(d2), "+f"(d3)
        : "r"(__float_as_uint(a0)), "r"(__float_as_uint(a1)),
          "r"(__float_as_uint(a2)), "r"(__float_as_uint(a3)),
          "r"(__float_as_uint(b0)), "r"(__float_as_uint(b1)));
}

__device__ __forceinline__ uint32_t tf32_rna(float x) {
    uint32_t u;
    asm("cvt.rna.tf32.f32 %0, %1;" : "=r"(u) : "f"(x));
    return u;
}

// ---------------------------------------------------------------------------
// Woodbury tail from the 8 fast-path sums (g purely imaginary form).
// ---------------------------------------------------------------------------
__device__ __forceinline__ float2 wb_fast(float SA, float SB, float SC, float SD,
                                          float TA, float TB, float TC, float TD,
                                          float pfr, float pfi)
{
    float PRBr = SA + TB, PRBi = SB - TA;
    float BRPr = SA - TB, BRPi = -SB - TA;
    float qr = 1.0f + SC, qi = -TC;
    float BRBr = SD, BRBi = -TD;
    float iq = 1.0f / (qr * qr + qi * qi);
    float numr = BRPr * PRBr - BRPi * PRBi;
    float numi = BRPr * PRBi + BRPi * PRBr;
    float tr = (numr * qr + numi * qi) * iq;
    float ti = (numi * qr - numr * qi) * iq;
    float hr = BRBr - tr, hi = BRBi - ti;
    return make_float2(pfr * hr - pfi * hi, pfr * hi + pfi * hr);
}

// ---------------------------------------------------------------------------
// Kernel 0: d-independent geometry table (replaces 2M redundant sincosf).
// ---------------------------------------------------------------------------
__global__ void geom_init()
{
    const int k = blockIdx.x * 256 + threadIdx.x;
    const float w0 = (float)(-6.283185307179586476925286766559 / (double)SEQ_L);
    float zs, zc;
    sincosf(w0 * (float)k, &zs, &zc);
    float dzr = 1.0f + zc, dzi = zs;
    if (k == HALF_L) { dzr = 1.1920929e-7f; dzi = 0.0f; }
    float idm = 1.0f / (dzr * dzr + dzi * dzi);
    float nr = 1.0f - zc, ni = -zs;
    float tanv = (ni * dzr - nr * dzi) * idm;   // Im((1-z)/(1+z))
    g_geom[k] = make_float4(tanv, 2.0f * dzr * idm, -2.0f * dzi * idm, 0.0f);
}

// ---------------------------------------------------------------------------
// Kernel 1: Cauchy + Woodbury via tf32 mma.sync.
// R14: geometry from table; paired-tile full-warp Woodbury epilogue.
// ---------------------------------------------------------------------------
__global__ void __launch_bounds__(256, 5) cauchy_mma(
    const float* __restrict__ Lam_re, const float* __restrict__ Lam_im,
    const float* __restrict__ P_re,   const float* __restrict__ P_im,
    const float* __restrict__ B_re,   const float* __restrict__ B_im,
    const float* __restrict__ log_dt)
{
    __shared__ float2 s_lisp[STATE_N];       // (lam_im, sp*sp) [init temp]
    __shared__ float  s_Sw[4 * STATE_N];     // tf32-rna S-weights [init temp]
    __shared__ float  s_Tw[4 * STATE_N];     // tf32-rna T-weights [init temp]
    __shared__ float4 s_lam4[32];            // [ch*4+qr] = (liA, sp2A, liB, sp2B)
    __shared__ float4 s_bf4[256];            // [(j*8+ch)*4+qr] = (S0,S1,T0,T1)
    __shared__ float  s_gi[1024];
    __shared__ float  s_sums[8][8][36];      // [warp][sum-col][kloc 0..31 +pad]
    __shared__ float  s_scal_sh;

    const int d    = blockIdx.y;
    const int seg  = blockIdx.x;
    const int tid  = threadIdx.x;
    const int lane = tid & 31;
    const int warp = tid >> 5;

    if (tid < STATE_N) {
        const int idx = d * STATE_N + tid;
        float lr = Lam_re[idx];
        float li = Lam_im[idx];
        float sp = fmaxf(lr, 0.0f) + log1pf(expf(-fabsf(lr)));  // softplus
        float pr = P_re[idx], pi = P_im[idx];
        float br = B_re[idx], bi = B_im[idx];
        float w1r = pr * br + pi * bi;    // conj(P)*B
        float w1i = pr * bi - pi * br;
        float pp  = pr * pr + pi * pi;
        float bb  = br * br + bi * bi;
        s_lisp[tid] = make_float2(li, sp * sp);
        s_Sw[0 * STATE_N + tid] = __uint_as_float(tf32_rna(w1r * sp));
        s_Sw[1 * STATE_N + tid] = __uint_as_float(tf32_rna(w1i * sp));
        s_Sw[2 * STATE_N + tid] = __uint_as_float(tf32_rna(pp * sp));
        s_Sw[3 * STATE_N + tid] = __uint_as_float(tf32_rna(bb * sp));
        s_Tw[0 * STATE_N + tid] = __uint_as_float(tf32_rna(w1r));
        s_Tw[1 * STATE_N + tid] = __uint_as_float(tf32_rna(w1i));
        s_Tw[2 * STATE_N + tid] = __uint_as_float(tf32_rna(pp));
        s_Tw[3 * STATE_N + tid] = __uint_as_float(tf32_rna(bb));
    }
    if (tid == 0) s_scal_sh = 2.0f * expf(-log_dt[d]);
    __syncthreads();

    // Pack per-chunk constants into float4 tables.
    if (tid < 32) {
        int ch = tid >> 2, q = tid & 3;
        int n0 = ch * 8 + q, n1 = n0 + 4;
        float2 a = s_lisp[n0];
        float2 b = s_lisp[n1];
        s_lam4[tid] = make_float4(a.x, a.y, b.x, b.y);
    }
    {
        int t = tid;                      // 256 entries: j(8) x ch(8) x qr(4)
        int jj = t >> 5, ch = (t >> 2) & 7, q = t & 3;
        int n0 = ch * 8 + q, n1 = n0 + 4;
        float4 v;
        if (jj < 4) v = make_float4(s_Sw[jj * STATE_N + n0],
                                    s_Sw[jj * STATE_N + n1], 0.f, 0.f);
        else        v = make_float4(0.f, 0.f,
                                    s_Tw[(jj - 4) * STATE_N + n0],
                                    s_Tw[(jj - 4) * STATE_N + n1]);
        s_bf4[t] = v;
    }

    // per-k prologue from the geometry table
    const float scal = s_scal_sh;
    for (int kk = tid; kk < 1024; kk += 256) {
        float4 gm = g_geom[seg * 1024 + kk];
        s_gi[kk] = scal * gm.x;
    }
    __syncthreads();

    const int j  = lane >> 2;       // B-fragment column 0..7
    const int qr = lane & 3;
    float* swp = &s_sums[warp][0][0];

    for (int tp = 0; tp < 4; tp++) {
#pragma unroll
        for (int half = 0; half < 2; half++) {
            const int t = tp * 2 + half;
            const int base = (warp * 8 + t) * 16;
            const float gi0 = s_gi[base + (lane >> 2)];       // row l/4
            const float gi1 = s_gi[base + 8 + (lane >> 2)];   // row 8 + l/4

            float dS0 = 0.f, dS1 = 0.f, dS2 = 0.f, dS3 = 0.f;
            float dT0 = 0.f, dT1 = 0.f, dT2 = 0.f, dT3 = 0.f;

#pragma unroll
            for (int ch = 0; ch < 8; ch++) {
                float4 lam = s_lam4[ch * 4 + qr];
                float4 bf  = s_bf4[(j * 8 + ch) * 4 + qr];

                float di0 = gi0 - lam.x;
                float di1 = gi1 - lam.x;
                float di2 = gi0 - lam.z;
                float di3 = gi1 - lam.z;
                float m0 = fmaf(di0, di0, lam.y);
                float m1 = fmaf(di1, di1, lam.y);
                float m2 = fmaf(di2, di2, lam.w);
                float m3 = fmaf(di3, di3, lam.w);
                float p01, p23;
                float q01 = m0 * m1, q23 = m2 * m3;
                asm("rcp.approx.f32 %0, %1;" : "=f"(p01) : "f"(q01));
                asm("rcp.approx.f32 %0, %1;" : "=f"(p23) : "f"(q23));
                float i0 = p01 * m1, i1 = p01 * m0;
                float i2 = p23 * m3, i3 = p23 * m2;
                float r0 = di0 * i0, r1 = di1 * i1;
                float r2 = di2 * i2, r3 = di3 * i3;

                mma_tf32(dS0, dS1, dS2, dS3, i0, i1, i2, i3, bf.x, bf.y);
                mma_tf32(dT0, dT1, dT2, dT3, r0, r1, r2, r3, bf.z, bf.w);
            }

            float d0 = dS0 + dT0, d1 = dS1 + dT1;
            float d2 = dS2 + dT2, d3 = dS3 + dT3;

            // stage into [col][kloc] (pad 36): conflict-free STS/LDS
            int kl0 = half * 16 + (lane >> 2);
            swp[(2 * qr)     * 36 + kl0]     = d0;
            swp[(2 * qr + 1) * 36 + kl0]     = d1;
            swp[(2 * qr)     * 36 + kl0 + 8] = d2;
            swp[(2 * qr + 1) * 36 + kl0 + 8] = d3;
        }

        __syncwarp();
        // full-warp Woodbury over the pair's 32 k-points
        {
            int kloc = lane;
            float SA = swp[0 * 36 + kloc];
            float SB = swp[1 * 36 + kloc];
            float SC = swp[2 * 36 + kloc];
            float SD = swp[3 * 36 + kloc];
            float TA = swp[4 * 36 + kloc];
            float TB = swp[5 * 36 + kloc];
            float TC = swp[6 * 36 + kloc];
            float TD = swp[7 * 36 + kloc];
            int kk = warp * 128 + tp * 32 + lane;
            float4 gm = g_geom[seg * 1024 + kk];
            float2 r = wb_fast(SA, SB, SC, SD, TA, TB, TC, TD, gm.y, gm.z);
            g_Khat[d * SEQ_L + seg * 1024 + kk] = r;
        }
        __syncwarp();
    }

    // ---- exact fix of the eps-clamped point k = L/2 (tid 0 of seg 4 wrote
    // it above; same thread overwrites in program order) ----
    if (seg == 4 && tid == 0) {
        const float w0 = (float)(-6.283185307179586476925286766559 / (double)SEQ_L);
        float zs, zc;
        sincosf(w0 * (float)HALF_L, &zs, &zc);
        float dzr = 1.1920929e-7f, dzi = 0.0f;
        float idm = 1.0f / (dzr * dzr + dzi * dzi);
        float nr = 1.0f - zc, ni = -zs;
        float gr = scal * (nr * dzr + ni * dzi) * idm;
        float gi = scal * (ni * dzr - nr * dzi) * idm;
        float pfr = 2.0f * dzr * idm, pfi = -2.0f * dzi * idm;

        float PRBr=0,PRBi=0,BRPr=0,BRPi=0,PRPr=0,PRPi=0,BRBr=0,BRBi=0;
        for (int n = 0; n < STATE_N; n++) {
            const int idx = d * STATE_N + n;
            float lr = Lam_re[idx];
            float li = Lam_im[idx];
            float sp = fmaxf(lr, 0.0f) + log1pf(expf(-fabsf(lr)));
            float pr = P_re[idx], pi = P_im[idx];
            float br = B_re[idx], bi = B_im[idx];
            float w1r = pr * br + pi * bi;
            float w1i = pr * bi - pi * br;
            float pp  = pr * pr + pi * pi;
            float bb  = br * br + bi * bi;
            float dr = gr + sp;
            float di = gi - li;
            float m  = fmaf(dr, dr, di * di);
            float inv = 1.0f / m;
            float Rtr = dr * inv;
            float Rti = -di * inv;
            PRBr += w1r * Rtr - w1i * Rti;
            PRBi += w1r * Rti + w1i * Rtr;
            BRPr += w1r * Rtr + w1i * Rti;
            BRPi += w1r * Rti - w1i * Rtr;
            PRPr += pp * Rtr;  PRPi += pp * Rti;
            BRBr += bb * Rtr;  BRBi += bb * Rti;
        }
        float qr2 = 1.0f + PRPr, qi2 = PRPi;
        float iq = 1.0f / (qr2 * qr2 + qi2 * qi2);
        float numr = BRPr * PRBr - BRPi * PRBi;
        float numi = BRPr * PRBi + BRPi * PRBr;
        float tr = (numr * qr2 + numi * qi2) * iq;
        float ti = (numi * qr2 - numr * qi2) * iq;
        float hr = BRBr - tr, hi = BRBi - ti;
        g_Khat[d * SEQ_L + HALF_L] = make_float2(pfr * hr - pfi * hi,
                                                 pfr * hi + pfi * hr);
    }
}

// ---------------------------------------------------------------------------
// Profiling positioner (keeps cauchy in ncu's captured slot = launch #4).
// ---------------------------------------------------------------------------
__global__ void dummy_a() {}

// ---------------------------------------------------------------------------
// Kernel 2: Re(ifft_L(X)) = Hermitian fold + 4096-pt radix-4 inverse Stockham.
// One CTA per d-row, 64 KB smem ping-pong, 1024 threads.
// ---------------------------------------------------------------------------
__global__ void __launch_bounds__(1024) ifft_kernel(float* __restrict__ out)
{
    extern __shared__ float2 sm[];
    float2* x = sm;
    float2* y = sm + HALF_L;

    const int d   = blockIdx.x;
    const int tid = threadIdx.x;
    const int NT  = 1024;

    const float2* src = g_Khat + d * SEQ_L;

    // Hermitian fold + even/odd pack:  x[k] = E[k] + i*O[k]
    const float thL = 6.28318530717958647692f / (float)SEQ_L;
    for (int kk = tid; kk < HALF_L; kk += NT) {
        float2 Xa  = src[kk];
        float2 Xam = src[kk == 0 ? 0 : SEQ_L - kk];
        float2 Xb  = src[kk + HALF_L];
        float2 Xbm = src[HALF_L - kk];
        float Ar = 0.5f * (Xa.x + Xam.x), Ai = 0.5f * (Xa.y - Xam.y);
        float Br = 0.5f * (Xb.x + Xbm.x), Bi = 0.5f * (Xb.y - Xbm.y);
        float Er = 0.5f * (Ar + Br), Ei = 0.5f * (Ai + Bi);
        float Dr = 0.5f * (Ar - Br), Di = 0.5f * (Ai - Bi);
        float swr, swi;
        __sincosf(thL * (float)kk, &swi, &swr);
        float Or = Dr * swr - Di * swi;
        float Oi = Dr * swi + Di * swr;
        x[kk] = make_float2(Er - Oi, Ei + Or);
    }
    __syncthreads();

    int n = HALF_L, s = 1, ls = 0;
    while (n > 1) {
        const int m = n >> 2;
        const float th = 6.28318530717958647692f / (float)n;
        for (int u = tid; u < (HALF_L >> 2); u += NT) {
            int p = u >> ls;
            int q = u & (s - 1);
            int base = q + s * p;
            float2 a  = x[base];
            float2 b  = x[base + s * m];
            float2 c  = x[base + s * 2 * m];
            float2 dd = x[base + s * 3 * m];

            float w1i, w1r;
            __sincosf(th * (float)p, &w1i, &w1r);
            float w2r = w1r * w1r - w1i * w1i;
            float w2i = 2.0f * w1r * w1i;
            float w3r = w2r * w1r - w2i * w1i;
            float w3i = w2r * w1i + w2i * w1r;

            float acr = a.x + c.x, aci = a.y + c.y;
            float amr = a.x - c.x, ami = a.y - c.y;
            float bdr = b.x + dd.x, bdi = b.y + dd.y;
            float bmr = b.x - dd.x, bmi = b.y - dd.y;

            float X0r = acr + bdr, X0i = aci + bdi;
            float X2r = acr - bdr, X2i = aci - bdi;
            float X1r = amr - bmi, X1i = ami + bmr;
            float X3r = amr + bmi, X3i = ami - bmr;

            int ob = q + s * 4 * p;
            y[ob]         = make_float2(X0r, X0i);
            y[ob + s]     = make_float2(X1r * w1r - X1i * w1i,
                                        X1r * w1i + X1i * w1r);
            y[ob + 2 * s] = make_float2(X2r * w2r - X2i * w2i,
                                        X2r * w2i + X2i * w2r);
            y[ob + 3 * s] = make_float2(X3r * w3r - X3i * w3i,
                                        X3r * w3i + X3i * w3r);
        }
        __syncthreads();
        float2* tmp = x; x = y; y = tmp;
        n = m; s <<= 2; ls += 2;
    }

    const float scale = 1.0f / (float)HALF_L;
    float* dstp = out + d * SEQ_L;
    for (int mI = tid; mI < HALF_L; mI += NT) {
        float2 v = x[mI];
        dstp[2 * mI]     = v.x * scale;
        dstp[2 * mI + 1] = v.y * scale;
    }
}

// ---------------------------------------------------------------------------
extern "C" void kernel_launch(void* const* d_in, const int* in_sizes, int n_in,
                              void* d_out, int out_size)
{
    const float* Lam_re = (const float*)d_in[0];
    const float* Lam_im = (const float*)d_in[1];
    const float* P_re   = (const float*)d_in[2];
    const float* P_im   = (const float*)d_in[3];
    const float* B_re   = (const float*)d_in[4];
    const float* B_im   = (const float*)d_in[5];
    const float* log_dt = (const float*)d_in[6];

    float* out = (float*)d_out;

    // Stage 0: geometry table (d-independent)
    geom_init<<<SEQ_L / 256, 256>>>();

    // Stage 1: Cauchy + Woodbury via tf32 MMA (incl. exact k=L/2 fix)
    dim3 gridA(SEQ_L / 1024, D_MODEL);   // 8 x 256
    cauchy_mma<<<gridA, 256>>>(Lam_re, Lam_im, P_re, P_im, B_re, B_im, log_dt);

    // Stage 2: Hermitian fold + radix-4 half-length iFFT per row -> K
    cudaFuncSetAttribute(ifft_kernel,
                         cudaFuncAttributeMaxDynamicSharedMemorySize, 65536);
    ifft_kernel<<<D_MODEL, 1024, 65536>>>(out);

    // keep cauchy in the ncu capture slot
    dummy_a<<<1, 32>>>();

    // Tail of the output: D buffer (zeros in the reference)
    long kElems = (long)D_MODEL * SEQ_L;
    if ((long)out_size > kElems) {
        cudaMemsetAsync(out + kElems, 0,
                        ((long)out_size - kElems) * sizeof(float), 0);
    }
}

// round 15
// speedup vs baseline: 1.0914x; 1.0134x over previous
#include <cuda_runtime.h>
#include <math.h>
#include <stdint.h>

#define D_MODEL 256
#define STATE_N 64
#define SEQ_L   8192
#define HALF_L  4096

// Scratch: K_hat[d, L] complex64 (16 MB) + geometry table (d-independent).
__device__ float2 g_Khat[D_MODEL * SEQ_L];
__device__ float4 g_geom[SEQ_L];   // (tanv, pfr, pfi, 0)

// ---------------------------------------------------------------------------
// tf32 mma (operands: raw f32 bits; HW ignores low 13 mantissa bits = trunc)
// ---------------------------------------------------------------------------
__device__ __forceinline__ void mma_tf32(float& d0, float& d1, float& d2, float& d3,
                                         float a0, float a1, float a2, float a3,
                                         float b0, float b1)
{
    asm volatile(
        "mma.sync.aligned.m16n8k8.row.col.f32.tf32.tf32.f32 "
        "{%0,%1,%2,%3}, {%4,%5,%6,%7}, {%8,%9}, {%0,%1,%2,%3};"
        : "+f"(d0), "+f"(d1), "+f"(d2), "+f"(d3)
        : "r"(__float_as_uint(a0)), "r"(__float_as_uint(a1)),
          "r"(__float_as_uint(a2)), "r"(__float_as_uint(a3)),
          "r"(__float_as_uint(b0)), "r"(__float_as_uint(b1)));
}

__device__ __forceinline__ uint32_t tf32_rna(float x) {
    uint32_t u;
    asm("cvt.rna.tf32.f32 %0, %1;" : "=r"(u) : "f"(x));
    return u;
}

// ---------------------------------------------------------------------------
// Woodbury tail from the 8 fast-path sums (g purely imaginary form).
// ---------------------------------------------------------------------------
__device__ __forceinline__ float2 wb_fast(float SA, float SB, float SC, float SD,
                                          float TA, float TB, float TC, float TD,
                                          float pfr, float pfi)
{
    float PRBr = SA + TB, PRBi = SB - TA;
    float BRPr = SA - TB, BRPi = -SB - TA;
    float qr = 1.0f + SC, qi = -TC;
    float BRBr = SD, BRBi = -TD;
    float iq = 1.0f / (qr * qr + qi * qi);
    float numr = BRPr * PRBr - BRPi * PRBi;
    float numi = BRPr * PRBi + BRPi * PRBr;
    float tr = (numr * qr + numi * qi) * iq;
    float ti = (numi * qr - numr * qi) * iq;
    float hr = BRBr - tr, hi = BRBi - ti;
    return make_float2(pfr * hr - pfi * hi, pfr * hi + pfi * hr);
}

// ---------------------------------------------------------------------------
// Kernel 0: d-independent geometry table (replaces 2M redundant sincosf).
// ---------------------------------------------------------------------------
__global__ void geom_init()
{
    const int k = blockIdx.x * 256 + threadIdx.x;
    const float w0 = (float)(-6.283185307179586476925286766559 / (double)SEQ_L);
    float zs, zc;
    sincosf(w0 * (float)k, &zs, &zc);
    float dzr = 1.0f + zc, dzi = zs;
    if (k == HALF_L) { dzr = 1.1920929e-7f; dzi = 0.0f; }
    float idm = 1.0f / (dzr * dzr + dzi * dzi);
    float nr = 1.0f - zc, ni = -zs;
    float tanv = (ni * dzr - nr * dzi) * idm;   // Im((1-z)/(1+z))
    g_geom[k] = make_float4(tanv, 2.0f * dzr * idm, -2.0f * dzi * idm, 0.0f);
}

// ---------------------------------------------------------------------------
// Kernel 1: Cauchy + Woodbury via tf32 mma.sync.
// R15: 6 CTAs/SM (regs capped at 42) for better latency coverage.
// ---------------------------------------------------------------------------
__global__ void __launch_bounds__(256, 6) cauchy_mma(
    const float* __restrict__ Lam_re, const float* __restrict__ Lam_im,
    const float* __restrict__ P_re,   const float* __restrict__ P_im,
    const float* __restrict__ B_re,   const float* __restrict__ B_im,
    const float* __restrict__ log_dt)
{
    __shared__ float2 s_lisp[STATE_N];       // (lam_im, sp*sp) [init temp]
    __shared__ float  s_Sw[4 * STATE_N];     // tf32-rna S-weights [init temp]
    __shared__ float  s_Tw[4 * STATE_N];     // tf32-rna T-weights [init temp]
    __shared__ float4 s_lam4[32];            // [ch*4+qr] = (liA, sp2A, liB, sp2B)
    __shared__ float4 s_bf4[256];            // [(j*8+ch)*4+qr] = (S0,S1,T0,T1)
    __shared__ float  s_gi[1024];
    __shared__ float  s_sums[8][8][36];      // [warp][sum-col][kloc 0..31 +pad]
    __shared__ float  s_scal_sh;

    const int d    = blockIdx.y;
    const int seg  = blockIdx.x;
    const int tid  = threadIdx.x;
    const int lane = tid & 31;
    const int warp = tid >> 5;

    if (tid < STATE_N) {
        const int idx = d * STATE_N + tid;
        float lr = Lam_re[idx];
        float li = Lam_im[idx];
        float sp = fmaxf(lr, 0.0f) + log1pf(expf(-fabsf(lr)));  // softplus
        float pr = P_re[idx], pi = P_im[idx];
        float br = B_re[idx], bi = B_im[idx];
        float w1r = pr * br + pi * bi;    // conj(P)*B
        float w1i = pr * bi - pi * br;
        float pp  = pr * pr + pi * pi;
        float bb  = br * br + bi * bi;
        s_lisp[tid] = make_float2(li, sp * sp);
        s_Sw[0 * STATE_N + tid] = __uint_as_float(tf32_rna(w1r * sp));
        s_Sw[1 * STATE_N + tid] = __uint_as_float(tf32_rna(w1i * sp));
        s_Sw[2 * STATE_N + tid] = __uint_as_float(tf32_rna(pp * sp));
        s_Sw[3 * STATE_N + tid] = __uint_as_float(tf32_rna(bb * sp));
        s_Tw[0 * STATE_N + tid] = __uint_as_float(tf32_rna(w1r));
        s_Tw[1 * STATE_N + tid] = __uint_as_float(tf32_rna(w1i));
        s_Tw[2 * STATE_N + tid] = __uint_as_float(tf32_rna(pp));
        s_Tw[3 * STATE_N + tid] = __uint_as_float(tf32_rna(bb));
    }
    if (tid == 0) s_scal_sh = 2.0f * expf(-log_dt[d]);
    __syncthreads();

    // Pack per-chunk constants into float4 tables.
    if (tid < 32) {
        int ch = tid >> 2, q = tid & 3;
        int n0 = ch * 8 + q, n1 = n0 + 4;
        float2 a = s_lisp[n0];
        float2 b = s_lisp[n1];
        s_lam4[tid] = make_float4(a.x, a.y, b.x, b.y);
    }
    {
        int t = tid;                      // 256 entries: j(8) x ch(8) x qr(4)
        int jj = t >> 5, ch = (t >> 2) & 7, q = t & 3;
        int n0 = ch * 8 + q, n1 = n0 + 4;
        float4 v;
        if (jj < 4) v = make_float4(s_Sw[jj * STATE_N + n0],
                                    s_Sw[jj * STATE_N + n1], 0.f, 0.f);
        else        v = make_float4(0.f, 0.f,
                                    s_Tw[(jj - 4) * STATE_N + n0],
                                    s_Tw[(jj - 4) * STATE_N + n1]);
        s_bf4[t] = v;
    }

    // per-k prologue from the geometry table
    const float scal = s_scal_sh;
    for (int kk = tid; kk < 1024; kk += 256) {
        float4 gm = g_geom[seg * 1024 + kk];
        s_gi[kk] = scal * gm.x;
    }
    __syncthreads();

    const int j  = lane >> 2;       // B-fragment column 0..7
    const int qr = lane & 3;
    float* swp = &s_sums[warp][0][0];

    for (int tp = 0; tp < 4; tp++) {
#pragma unroll
        for (int half = 0; half < 2; half++) {
            const int t = tp * 2 + half;
            const int base = (warp * 8 + t) * 16;
            const float gi0 = s_gi[base + (lane >> 2)];       // row l/4
            const float gi1 = s_gi[base + 8 + (lane >> 2)];   // row 8 + l/4

            float dS0 = 0.f, dS1 = 0.f, dS2 = 0.f, dS3 = 0.f;
            float dT0 = 0.f, dT1 = 0.f, dT2 = 0.f, dT3 = 0.f;

#pragma unroll
            for (int ch = 0; ch < 8; ch++) {
                float4 lam = s_lam4[ch * 4 + qr];
                float4 bf  = s_bf4[(j * 8 + ch) * 4 + qr];

                float di0 = gi0 - lam.x;
                float di1 = gi1 - lam.x;
                float di2 = gi0 - lam.z;
                float di3 = gi1 - lam.z;
                float m0 = fmaf(di0, di0, lam.y);
                float m1 = fmaf(di1, di1, lam.y);
                float m2 = fmaf(di2, di2, lam.w);
                float m3 = fmaf(di3, di3, lam.w);
                float p01, p23;
                float q01 = m0 * m1, q23 = m2 * m3;
                asm("rcp.approx.f32 %0, %1;" : "=f"(p01) : "f"(q01));
                asm("rcp.approx.f32 %0, %1;" : "=f"(p23) : "f"(q23));
                float i0 = p01 * m1, i1 = p01 * m0;
                float i2 = p23 * m3, i3 = p23 * m2;
                float r0 = di0 * i0, r1 = di1 * i1;
                float r2 = di2 * i2, r3 = di3 * i3;

                mma_tf32(dS0, dS1, dS2, dS3, i0, i1, i2, i3, bf.x, bf.y);
                mma_tf32(dT0, dT1, dT2, dT3, r0, r1, r2, r3, bf.z, bf.w);
            }

            float d0 = dS0 + dT0, d1 = dS1 + dT1;
            float d2 = dS2 + dT2, d3 = dS3 + dT3;

            // stage into [col][kloc] (pad 36): conflict-free STS/LDS
            int kl0 = half * 16 + (lane >> 2);
            swp[(2 * qr)     * 36 + kl0]     = d0;
            swp[(2 * qr + 1) * 36 + kl0]     = d1;
            swp[(2 * qr)     * 36 + kl0 + 8] = d2;
            swp[(2 * qr + 1) * 36 + kl0 + 8] = d3;
        }

        __syncwarp();
        // full-warp Woodbury over the pair's 32 k-points
        {
            int kloc = lane;
            float SA = swp[0 * 36 + kloc];
            float SB = swp[1 * 36 + kloc];
            float SC = swp[2 * 36 + kloc];
            float SD = swp[3 * 36 + kloc];
            float TA = swp[4 * 36 + kloc];
            float TB = swp[5 * 36 + kloc];
            float TC = swp[6 * 36 + kloc];
            float TD = swp[7 * 36 + kloc];
            int kk = warp * 128 + tp * 32 + lane;
            float4 gm = g_geom[seg * 1024 + kk];
            float2 r = wb_fast(SA, SB, SC, SD, TA, TB, TC, TD, gm.y, gm.z);
            g_Khat[d * SEQ_L + seg * 1024 + kk] = r;
        }
        __syncwarp();
    }

    // ---- exact fix of the eps-clamped point k = L/2 (tid 0 of seg 4 wrote
    // it above; same thread overwrites in program order) ----
    if (seg == 4 && tid == 0) {
        const float w0 = (float)(-6.283185307179586476925286766559 / (double)SEQ_L);
        float zs, zc;
        sincosf(w0 * (float)HALF_L, &zs, &zc);
        float dzr = 1.1920929e-7f, dzi = 0.0f;
        float idm = 1.0f / (dzr * dzr + dzi * dzi);
        float nr = 1.0f - zc, ni = -zs;
        float gr = scal * (nr * dzr + ni * dzi) * idm;
        float gi = scal * (ni * dzr - nr * dzi) * idm;
        float pfr = 2.0f * dzr * idm, pfi = -2.0f * dzi * idm;

        float PRBr=0,PRBi=0,BRPr=0,BRPi=0,PRPr=0,PRPi=0,BRBr=0,BRBi=0;
        for (int n = 0; n < STATE_N; n++) {
            const int idx = d * STATE_N + n;
            float lr = Lam_re[idx];
            float li = Lam_im[idx];
            float sp = fmaxf(lr, 0.0f) + log1pf(expf(-fabsf(lr)));
            float pr = P_re[idx], pi = P_im[idx];
            float br = B_re[idx], bi = B_im[idx];
            float w1r = pr * br + pi * bi;
            float w1i = pr * bi - pi * br;
            float pp  = pr * pr + pi * pi;
            float bb  = br * br + bi * bi;
            float dr = gr + sp;
            float di = gi - li;
            float m  = fmaf(dr, dr, di * di);
            float inv = 1.0f / m;
            float Rtr = dr * inv;
            float Rti = -di * inv;
            PRBr += w1r * Rtr - w1i * Rti;
            PRBi += w1r * Rti + w1i * Rtr;
            BRPr += w1r * Rtr + w1i * Rti;
            BRPi += w1r * Rti - w1i * Rtr;
            PRPr += pp * Rtr;  PRPi += pp * Rti;
            BRBr += bb * Rtr;  BRBi += bb * Rti;
        }
        float qr2 = 1.0f + PRPr, qi2 = PRPi;
        float iq = 1.0f / (qr2 * qr2 + qi2 * qi2);
        float numr = BRPr * PRBr - BRPi * PRBi;
        float numi = BRPr * PRBi + BRPi * PRBr;
        float tr = (numr * qr2 + numi * qi2) * iq;
        float ti = (numi * qr2 - numr * qi2) * iq;
        float hr = BRBr - tr, hi = BRBi - ti;
        g_Khat[d * SEQ_L + HALF_L] = make_float2(pfr * hr - pfi * hi,
                                                 pfr * hi + pfi * hr);
    }
}

// ---------------------------------------------------------------------------
// Kernel 2: Re(ifft_L(X)) = Hermitian fold + 4096-pt radix-4 inverse Stockham.
// One CTA per d-row, 64 KB smem ping-pong, 1024 threads.
// ---------------------------------------------------------------------------
__global__ void __launch_bounds__(1024) ifft_kernel(float* __restrict__ out)
{
    extern __shared__ float2 sm[];
    float2* x = sm;
    float2* y = sm + HALF_L;

    const int d   = blockIdx.x;
    const int tid = threadIdx.x;
    const int NT  = 1024;

    const float2* src = g_Khat + d * SEQ_L;

    // Hermitian fold + even/odd pack:  x[k] = E[k] + i*O[k]
    const float thL = 6.28318530717958647692f / (float)SEQ_L;
    for (int kk = tid; kk < HALF_L; kk += NT) {
        float2 Xa  = src[kk];
        float2 Xam = src[kk == 0 ? 0 : SEQ_L - kk];
        float2 Xb  = src[kk + HALF_L];
        float2 Xbm = src[HALF_L - kk];
        float Ar = 0.5f * (Xa.x + Xam.x), Ai = 0.5f * (Xa.y - Xam.y);
        float Br = 0.5f * (Xb.x + Xbm.x), Bi = 0.5f * (Xb.y - Xbm.y);
        float Er = 0.5f * (Ar + Br), Ei = 0.5f * (Ai + Bi);
        float Dr = 0.5f * (Ar - Br), Di = 0.5f * (Ai - Bi);
        float swr, swi;
        __sincosf(thL * (float)kk, &swi, &swr);
        float Or = Dr * swr - Di * swi;
        float Oi = Dr * swi + Di * swr;
        x[kk] = make_float2(Er - Oi, Ei + Or);
    }
    __syncthreads();

    int n = HALF_L, s = 1, ls = 0;
    while (n > 1) {
        const int m = n >> 2;
        const float th = 6.28318530717958647692f / (float)n;
        for (int u = tid; u < (HALF_L >> 2); u += NT) {
            int p = u >> ls;
            int q = u & (s - 1);
            int base = q + s * p;
            float2 a  = x[base];
            float2 b  = x[base + s * m];
            float2 c  = x[base + s * 2 * m];
            float2 dd = x[base + s * 3 * m];

            float w1i, w1r;
            __sincosf(th * (float)p, &w1i, &w1r);
            float w2r = w1r * w1r - w1i * w1i;
            float w2i = 2.0f * w1r * w1i;
            float w3r = w2r * w1r - w2i * w1i;
            float w3i = w2r * w1i + w2i * w1r;

            float acr = a.x + c.x, aci = a.y + c.y;
            float amr = a.x - c.x, ami = a.y - c.y;
            float bdr = b.x + dd.x, bdi = b.y + dd.y;
            float bmr = b.x - dd.x, bmi = b.y - dd.y;

            float X0r = acr + bdr, X0i = aci + bdi;
            float X2r = acr - bdr, X2i = aci - bdi;
            float X1r = amr - bmi, X1i = ami + bmr;
            float X3r = amr + bmi, X3i = ami - bmr;

            int ob = q + s * 4 * p;
            y[ob]         = make_float2(X0r, X0i);
            y[ob + s]     = make_float2(X1r * w1r - X1i * w1i,
                                        X1r * w1i + X1i * w1r);
            y[ob + 2 * s] = make_float2(X2r * w2r - X2i * w2i,
                                        X2r * w2i + X2i * w2r);
            y[ob + 3 * s] = make_float2(X3r * w3r - X3i * w3i,
                                        X3r * w3i + X3i * w3r);
        }
        __syncthreads();
        float2* tmp = x; x = y; y = tmp;
        n = m; s <<= 2; ls += 2;
    }

    const float scale = 1.0f / (float)HALF_L;
    float* dstp = out + d * SEQ_L;
    for (int mI = tid; mI < HALF_L; mI += NT) {
        float2 v = x[mI];
        dstp[2 * mI]     = v.x * scale;
        dstp[2 * mI + 1] = v.y * scale;
    }
}

// ---------------------------------------------------------------------------
extern "C" void kernel_launch(void* const* d_in, const int* in_sizes, int n_in,
                              void* d_out, int out_size)
{
    const float* Lam_re = (const float*)d_in[0];
    const float* Lam_im = (const float*)d_in[1];
    const float* P_re   = (const float*)d_in[2];
    const float* P_im   = (const float*)d_in[3];
    const float* B_re   = (const float*)d_in[4];
    const float* B_im   = (const float*)d_in[5];
    const float* log_dt = (const float*)d_in[6];

    float* out = (float*)d_out;

    // Stage 0: geometry table (d-independent)
    geom_init<<<SEQ_L / 256, 256>>>();

    // Stage 1: Cauchy + Woodbury via tf32 MMA (incl. exact k=L/2 fix)
    dim3 gridA(SEQ_L / 1024, D_MODEL);   // 8 x 256
    cauchy_mma<<<gridA, 256>>>(Lam_re, Lam_im, P_re, P_im, B_re, B_im, log_dt);

    // Stage 2: Hermitian fold + radix-4 half-length iFFT per row -> K
    cudaFuncSetAttribute(ifft_kernel,
                         cudaFuncAttributeMaxDynamicSharedMemorySize, 65536);
    ifft_kernel<<<D_MODEL, 1024, 65536>>>(out);

    // Tail of the output: D buffer (zeros in the reference)
    long kElems = (long)D_MODEL * SEQ_L;
    if ((long)out_size > kElems) {
        cudaMemsetAsync(out + kElems, 0,
                        ((long)out_size - kElems) * sizeof(float), 0);
    }
}

// round 16
// speedup vs baseline: 1.1043x; 1.0118x over previous
#include <cuda_runtime.h>
#include <math.h>
#include <stdint.h>

#define D_MODEL 256
#define STATE_N 64
#define SEQ_L   8192
#define HALF_L  4096

// Scratch: K_hat[d, L] complex64 (16 MB) + geometry table (d-independent).
__device__ float2 g_Khat[D_MODEL * SEQ_L];
__device__ float4 g_geom[SEQ_L];   // (tanv, pfr, pfi, 0)

// ---------------------------------------------------------------------------
// tf32 mma (operands: raw f32 bits; HW ignores low 13 mantissa bits = trunc)
// ---------------------------------------------------------------------------
__device__ __forceinline__ void mma_tf32(float& d0, float& d1, float& d2, float& d3,
                                         float a0, float a1, float a2, float a3,
                                         float b0, float b1)
{
    asm volatile(
        "mma.sync.aligned.m16n8k8.row.col.f32.tf32.tf32.f32 "
        "{%0,%1,%2,%3}, {%4,%5,%6,%7}, {%8,%9}, {%0,%1,%2,%3};"
        : "+f"(d0), "+f"(d1), "+f"(d2), "+f"(d3)
        : "r"(__float_as_uint(a0)), "r"(__float_as_uint(a1)),
          "r"(__float_as_uint(a2)), "r"(__float_as_uint(a3)),
          "r"(__float_as_uint(b0)), "r"(__float_as_uint(b1)));
}

__device__ __forceinline__ uint32_t tf32_rna(float x) {
    uint32_t u;
    asm("cvt.rna.tf32.f32 %0, %1;" : "=r"(u) : "f"(x));
    return u;
}

// ---------------------------------------------------------------------------
// Woodbury tail from the 8 fast-path sums (g purely imaginary form).
// ---------------------------------------------------------------------------
__device__ __forceinline__ float2 wb_fast(float SA, float SB, float SC, float SD,
                                          float TA, float TB, float TC, float TD,
                                          float pfr, float pfi)
{
    float PRBr = SA + TB, PRBi = SB - TA;
    float BRPr = SA - TB, BRPi = -SB - TA;
    float qr = 1.0f + SC, qi = -TC;
    float BRBr = SD, BRBi = -TD;
    float iq = 1.0f / (qr * qr + qi * qi);
    float numr = BRPr * PRBr - BRPi * PRBi;
    float numi = BRPr * PRBi + BRPi * PRBr;
    float tr = (numr * qr + numi * qi) * iq;
    float ti = (numi * qr - numr * qi) * iq;
    float hr = BRBr - tr, hi = BRBi - ti;
    return make_float2(pfr * hr - pfi * hi, pfr * hi + pfi * hr);
}

__device__ __forceinline__ float2 cmul(float2 a, float2 b) {
    return make_float2(a.x * b.x - a.y * b.y, a.x * b.y + a.y * b.x);
}

// ---------------------------------------------------------------------------
// Kernel 0: d-independent geometry table (replaces 2M redundant sincosf).
// ---------------------------------------------------------------------------
__global__ void geom_init()
{
    const int k = blockIdx.x * 256 + threadIdx.x;
    const float w0 = (float)(-6.283185307179586476925286766559 / (double)SEQ_L);
    float zs, zc;
    sincosf(w0 * (float)k, &zs, &zc);
    float dzr = 1.0f + zc, dzi = zs;
    if (k == HALF_L) { dzr = 1.1920929e-7f; dzi = 0.0f; }
    float idm = 1.0f / (dzr * dzr + dzi * dzi);
    float nr = 1.0f - zc, ni = -zs;
    float tanv = (ni * dzr - nr * dzi) * idm;   // Im((1-z)/(1+z))
    g_geom[k] = make_float4(tanv, 2.0f * dzr * idm, -2.0f * dzi * idm, 0.0f);
}

// ---------------------------------------------------------------------------
// Kernel 1: Cauchy + Woodbury via tf32 mma.sync (R14 config: 5 CTAs/SM).
// ---------------------------------------------------------------------------
__global__ void __launch_bounds__(256, 5) cauchy_mma(
    const float* __restrict__ Lam_re, const float* __restrict__ Lam_im,
    const float* __restrict__ P_re,   const float* __restrict__ P_im,
    const float* __restrict__ B_re,   const float* __restrict__ B_im,
    const float* __restrict__ log_dt)
{
    __shared__ float2 s_lisp[STATE_N];       // (lam_im, sp*sp) [init temp]
    __shared__ float  s_Sw[4 * STATE_N];     // tf32-rna S-weights [init temp]
    __shared__ float  s_Tw[4 * STATE_N];     // tf32-rna T-weights [init temp]
    __shared__ float4 s_lam4[32];            // [ch*4+qr] = (liA, sp2A, liB, sp2B)
    __shared__ float4 s_bf4[256];            // [(j*8+ch)*4+qr] = (S0,S1,T0,T1)
    __shared__ float  s_gi[1024];
    __shared__ float  s_sums[8][8][36];      // [warp][sum-col][kloc 0..31 +pad]
    __shared__ float  s_scal_sh;

    const int d    = blockIdx.y;
    const int seg  = blockIdx.x;
    const int tid  = threadIdx.x;
    const int lane = tid & 31;
    const int warp = tid >> 5;

    if (tid < STATE_N) {
        const int idx = d * STATE_N + tid;
        float lr = Lam_re[idx];
        float li = Lam_im[idx];
        float sp = fmaxf(lr, 0.0f) + log1pf(expf(-fabsf(lr)));  // softplus
        float pr = P_re[idx], pi = P_im[idx];
        float br = B_re[idx], bi = B_im[idx];
        float w1r = pr * br + pi * bi;    // conj(P)*B
        float w1i = pr * bi - pi * br;
        float pp  = pr * pr + pi * pi;
        float bb  = br * br + bi * bi;
        s_lisp[tid] = make_float2(li, sp * sp);
        s_Sw[0 * STATE_N + tid] = __uint_as_float(tf32_rna(w1r * sp));
        s_Sw[1 * STATE_N + tid] = __uint_as_float(tf32_rna(w1i * sp));
        s_Sw[2 * STATE_N + tid] = __uint_as_float(tf32_rna(pp * sp));
        s_Sw[3 * STATE_N + tid] = __uint_as_float(tf32_rna(bb * sp));
        s_Tw[0 * STATE_N + tid] = __uint_as_float(tf32_rna(w1r));
        s_Tw[1 * STATE_N + tid] = __uint_as_float(tf32_rna(w1i));
        s_Tw[2 * STATE_N + tid] = __uint_as_float(tf32_rna(pp));
        s_Tw[3 * STATE_N + tid] = __uint_as_float(tf32_rna(bb));
    }
    if (tid == 0) s_scal_sh = 2.0f * expf(-log_dt[d]);
    __syncthreads();

    // Pack per-chunk constants into float4 tables.
    if (tid < 32) {
        int ch = tid >> 2, q = tid & 3;
        int n0 = ch * 8 + q, n1 = n0 + 4;
        float2 a = s_lisp[n0];
        float2 b = s_lisp[n1];
        s_lam4[tid] = make_float4(a.x, a.y, b.x, b.y);
    }
    {
        int t = tid;                      // 256 entries: j(8) x ch(8) x qr(4)
        int jj = t >> 5, ch = (t >> 2) & 7, q = t & 3;
        int n0 = ch * 8 + q, n1 = n0 + 4;
        float4 v;
        if (jj < 4) v = make_float4(s_Sw[jj * STATE_N + n0],
                                    s_Sw[jj * STATE_N + n1], 0.f, 0.f);
        else        v = make_float4(0.f, 0.f,
                                    s_Tw[(jj - 4) * STATE_N + n0],
                                    s_Tw[(jj - 4) * STATE_N + n1]);
        s_bf4[t] = v;
    }

    // per-k prologue from the geometry table
    const float scal = s_scal_sh;
    for (int kk = tid; kk < 1024; kk += 256) {
        float4 gm = g_geom[seg * 1024 + kk];
        s_gi[kk] = scal * gm.x;
    }
    __syncthreads();

    const int j  = lane >> 2;       // B-fragment column 0..7
    const int qr = lane & 3;
    float* swp = &s_sums[warp][0][0];

    for (int tp = 0; tp < 4; tp++) {
#pragma unroll
        for (int half = 0; half < 2; half++) {
            const int t = tp * 2 + half;
            const int base = (warp * 8 + t) * 16;
            const float gi0 = s_gi[base + (lane >> 2)];       // row l/4
            const float gi1 = s_gi[base + 8 + (lane >> 2)];   // row 8 + l/4

            float dS0 = 0.f, dS1 = 0.f, dS2 = 0.f, dS3 = 0.f;
            float dT0 = 0.f, dT1 = 0.f, dT2 = 0.f, dT3 = 0.f;

#pragma unroll
            for (int ch = 0; ch < 8; ch++) {
                float4 lam = s_lam4[ch * 4 + qr];
                float4 bf  = s_bf4[(j * 8 + ch) * 4 + qr];

                float di0 = gi0 - lam.x;
                float di1 = gi1 - lam.x;
                float di2 = gi0 - lam.z;
                float di3 = gi1 - lam.z;
                float m0 = fmaf(di0, di0, lam.y);
                float m1 = fmaf(di1, di1, lam.y);
                float m2 = fmaf(di2, di2, lam.w);
                float m3 = fmaf(di3, di3, lam.w);
                float p01, p23;
                float q01 = m0 * m1, q23 = m2 * m3;
                asm("rcp.approx.f32 %0, %1;" : "=f"(p01) : "f"(q01));
                asm("rcp.approx.f32 %0, %1;" : "=f"(p23) : "f"(q23));
                float i0 = p01 * m1, i1 = p01 * m0;
                float i2 = p23 * m3, i3 = p23 * m2;
                float r0 = di0 * i0, r1 = di1 * i1;
                float r2 = di2 * i2, r3 = di3 * i3;

                mma_tf32(dS0, dS1, dS2, dS3, i0, i1, i2, i3, bf.x, bf.y);
                mma_tf32(dT0, dT1, dT2, dT3, r0, r1, r2, r3, bf.z, bf.w);
            }

            float d0 = dS0 + dT0, d1 = dS1 + dT1;
            float d2 = dS2 + dT2, d3 = dS3 + dT3;

            // stage into [col][kloc] (pad 36): conflict-free STS/LDS
            int kl0 = half * 16 + (lane >> 2);
            swp[(2 * qr)     * 36 + kl0]     = d0;
            swp[(2 * qr + 1) * 36 + kl0]     = d1;
            swp[(2 * qr)     * 36 + kl0 + 8] = d2;
            swp[(2 * qr + 1) * 36 + kl0 + 8] = d3;
        }

        __syncwarp();
        // full-warp Woodbury over the pair's 32 k-points
        {
            int kloc = lane;
            float SA = swp[0 * 36 + kloc];
            float SB = swp[1 * 36 + kloc];
            float SC = swp[2 * 36 + kloc];
            float SD = swp[3 * 36 + kloc];
            float TA = swp[4 * 36 + kloc];
            float TB = swp[5 * 36 + kloc];
            float TC = swp[6 * 36 + kloc];
            float TD = swp[7 * 36 + kloc];
            int kk = warp * 128 + tp * 32 + lane;
            float4 gm = g_geom[seg * 1024 + kk];
            float2 r = wb_fast(SA, SB, SC, SD, TA, TB, TC, TD, gm.y, gm.z);
            g_Khat[d * SEQ_L + seg * 1024 + kk] = r;
        }
        __syncwarp();
    }

    // ---- exact fix of the eps-clamped point k = L/2 (tid 0 of seg 4 wrote
    // it above; same thread overwrites in program order) ----
    if (seg == 4 && tid == 0) {
        const float w0 = (float)(-6.283185307179586476925286766559 / (double)SEQ_L);
        float zs, zc;
        sincosf(w0 * (float)HALF_L, &zs, &zc);
        float dzr = 1.1920929e-7f, dzi = 0.0f;
        float idm = 1.0f / (dzr * dzr + dzi * dzi);
        float nr = 1.0f - zc, ni = -zs;
        float gr = scal * (nr * dzr + ni * dzi) * idm;
        float gi = scal * (ni * dzr - nr * dzi) * idm;
        float pfr = 2.0f * dzr * idm, pfi = -2.0f * dzi * idm;

        float PRBr=0,PRBi=0,BRPr=0,BRPi=0,PRPr=0,PRPi=0,BRBr=0,BRBi=0;
        for (int n = 0; n < STATE_N; n++) {
            const int idx = d * STATE_N + n;
            float lr = Lam_re[idx];
            float li = Lam_im[idx];
            float sp = fmaxf(lr, 0.0f) + log1pf(expf(-fabsf(lr)));
            float pr = P_re[idx], pi = P_im[idx];
            float br = B_re[idx], bi = B_im[idx];
            float w1r = pr * br + pi * bi;
            float w1i = pr * bi - pi * br;
            float pp  = pr * pr + pi * pi;
            float bb  = br * br + bi * bi;
            float dr = gr + sp;
            float di = gi - li;
            float m  = fmaf(dr, dr, di * di);
            float inv = 1.0f / m;
            float Rtr = dr * inv;
            float Rti = -di * inv;
            PRBr += w1r * Rtr - w1i * Rti;
            PRBi += w1r * Rti + w1i * Rtr;
            BRPr += w1r * Rtr + w1i * Rti;
            BRPi += w1r * Rti - w1i * Rtr;
            PRPr += pp * Rtr;  PRPi += pp * Rti;
            BRBr += bb * Rtr;  BRBi += bb * Rti;
        }
        float qr2 = 1.0f + PRPr, qi2 = PRPi;
        float iq = 1.0f / (qr2 * qr2 + qi2 * qi2);
        float numr = BRPr * PRBr - BRPi * PRBi;
        float numi = BRPr * PRBi + BRPi * PRBr;
        float tr = (numr * qr2 + numi * qi2) * iq;
        float ti = (numi * qr2 - numr * qi2) * iq;
        float hr = BRBr - tr, hi = BRBi - ti;
        g_Khat[d * SEQ_L + HALF_L] = make_float2(pfr * hr - pfi * hi,
                                                 pfr * hi + pfi * hr);
    }
}

// ---------------------------------------------------------------------------
// Kernel 2: Re(ifft_L(X)) = Hermitian fold + 4096-pt RADIX-8 inverse Stockham
// (4 stages). 512 threads = 1 butterfly/thread/stage. Also zeroes the D-tail
// of the output (folds the memset node).
// ---------------------------------------------------------------------------
__global__ void __launch_bounds__(512) ifft_kernel(float* __restrict__ out,
                                                   int tail)
{
    extern __shared__ float2 sm[];
    float2* x = sm;
    float2* y = sm + HALF_L;

    const int d   = blockIdx.x;
    const int tid = threadIdx.x;
    const int NT  = 512;
    const float C = 0.70710678118654752440f;   // sqrt(2)/2

    const float2* src = g_Khat + d * SEQ_L;

    // Fold the output tail zeroing into block 0 (replaces cudaMemsetAsync).
    if (d == 0 && tid < tail)
        out[D_MODEL * SEQ_L + tid] = 0.0f;

    // Hermitian fold + even/odd pack:  x[k] = E[k] + i*O[k]
    const float thL = 6.28318530717958647692f / (float)SEQ_L;
    for (int kk = tid; kk < HALF_L; kk += NT) {
        float2 Xa  = src[kk];
        float2 Xam = src[kk == 0 ? 0 : SEQ_L - kk];
        float2 Xb  = src[kk + HALF_L];
        float2 Xbm = src[HALF_L - kk];
        float Ar = 0.5f * (Xa.x + Xam.x), Ai = 0.5f * (Xa.y - Xam.y);
        float Br = 0.5f * (Xb.x + Xbm.x), Bi = 0.5f * (Xb.y - Xbm.y);
        float Er = 0.5f * (Ar + Br), Ei = 0.5f * (Ai + Bi);
        float Dr = 0.5f * (Ar - Br), Di = 0.5f * (Ai - Bi);
        float swr, swi;
        __sincosf(thL * (float)kk, &swi, &swr);
        float Or = Dr * swr - Di * swi;
        float Oi = Dr * swi + Di * swr;
        x[kk] = make_float2(Er - Oi, Ei + Or);
    }
    __syncthreads();

    // 4 radix-8 inverse Stockham stages (4096 = 8^4), e^{+} twiddles
    int n = HALF_L, s = 1, ls = 0;
    while (n > 1) {
        const int m = n >> 3;
        const float th = 6.28318530717958647692f / (float)n;
        {
            const int u = tid;              // exactly 512 butterflies
            int p = u >> ls;
            int q = u & (s - 1);
            int base = q + s * p;
            int st = s * m;
            float2 t0 = x[base];
            float2 t1 = x[base + st];
            float2 t2 = x[base + 2 * st];
            float2 t3 = x[base + 3 * st];
            float2 t4 = x[base + 4 * st];
            float2 t5 = x[base + 5 * st];
            float2 t6 = x[base + 6 * st];
            float2 t7 = x[base + 7 * st];

            float2 u0 = make_float2(t0.x + t4.x, t0.y + t4.y);
            float2 u1 = make_float2(t1.x + t5.x, t1.y + t5.y);
            float2 u2 = make_float2(t2.x + t6.x, t2.y + t6.y);
            float2 u3 = make_float2(t3.x + t7.x, t3.y + t7.y);
            float2 v0 = make_float2(t0.x - t4.x, t0.y - t4.y);
            float2 v1 = make_float2(t1.x - t5.x, t1.y - t5.y);
            float2 v2 = make_float2(t2.x - t6.x, t2.y - t6.y);
            float2 v3 = make_float2(t3.x - t7.x, t3.y - t7.y);

            // v twiddles: e^{+i pi t/4}, t = 1,2,3
            float2 v1p = make_float2(C * (v1.x - v1.y), C * (v1.x + v1.y));
            float2 v2p = make_float2(-v2.y, v2.x);
            float2 v3p = make_float2(-C * (v3.x + v3.y), C * (v3.x - v3.y));

            // DFT4+ on u -> X0, X2, X4, X6
            float2 e0 = make_float2(u0.x + u2.x, u0.y + u2.y);
            float2 e1 = make_float2(u0.x - u2.x, u0.y - u2.y);
            float2 o0 = make_float2(u1.x + u3.x, u1.y + u3.y);
            float2 o1 = make_float2(u1.x - u3.x, u1.y - u3.y);
            float2 X0 = make_float2(e0.x + o0.x, e0.y + o0.y);
            float2 X4 = make_float2(e0.x - o0.x, e0.y - o0.y);
            float2 X2 = make_float2(e1.x - o1.y, e1.y + o1.x);
            float2 X6 = make_float2(e1.x + o1.y, e1.y - o1.x);

            // DFT4+ on v' -> X1, X3, X5, X7
            float2 f0 = make_float2(v0.x + v2p.x, v0.y + v2p.y);
            float2 f1 = make_float2(v0.x - v2p.x, v0.y - v2p.y);
            float2 g0 = make_float2(v1p.x + v3p.x, v1p.y + v3p.y);
            float2 g1 = make_float2(v1p.x - v3p.x, v1p.y - v3p.y);
            float2 X1 = make_float2(f0.x + g0.x, f0.y + g0.y);
            float2 X5 = make_float2(f0.x - g0.x, f0.y - g0.y);
            float2 X3 = make_float2(f1.x - g1.y, f1.y + g1.x);
            float2 X7 = make_float2(f1.x + g1.y, f1.y - g1.x);

            // output twiddles w^t, w = e^{+i th p}
            float w1i, w1r;
            __sincosf(th * (float)p, &w1i, &w1r);
            float2 w1 = make_float2(w1r, w1i);
            float2 w2 = cmul(w1, w1);
            float2 w3 = cmul(w2, w1);
            float2 w4 = cmul(w2, w2);
            float2 w5 = cmul(w3, w2);
            float2 w6 = cmul(w3, w3);
            float2 w7 = cmul(w4, w3);

            int ob = q + s * 8 * p;
            y[ob]         = X0;
            y[ob + s]     = cmul(X1, w1);
            y[ob + 2 * s] = cmul(X2, w2);
            y[ob + 3 * s] = cmul(X3, w3);
            y[ob + 4 * s] = cmul(X4, w4);
            y[ob + 5 * s] = cmul(X5, w5);
            y[ob + 6 * s] = cmul(X6, w6);
            y[ob + 7 * s] = cmul(X7, w7);
        }
        __syncthreads();
        float2* tmp = x; x = y; y = tmp;
        n = m; s <<= 3; ls += 3;
    }

    // x[m] = K[2m] + i*K[2m+1]  ->  interleaved real output
    const float scale = 1.0f / (float)HALF_L;
    float* dstp = out + d * SEQ_L;
    for (int mI = tid; mI < HALF_L; mI += NT) {
        float2 v = x[mI];
        dstp[2 * mI]     = v.x * scale;
        dstp[2 * mI + 1] = v.y * scale;
    }
}

// ---------------------------------------------------------------------------
extern "C" void kernel_launch(void* const* d_in, const int* in_sizes, int n_in,
                              void* d_out, int out_size)
{
    const float* Lam_re = (const float*)d_in[0];
    const float* Lam_im = (const float*)d_in[1];
    const float* P_re   = (const float*)d_in[2];
    const float* P_im   = (const float*)d_in[3];
    const float* B_re   = (const float*)d_in[4];
    const float* B_im   = (const float*)d_in[5];
    const float* log_dt = (const float*)d_in[6];

    float* out = (float*)d_out;

    // Stage 0: geometry table (d-independent)
    geom_init<<<SEQ_L / 256, 256>>>();

    // Stage 1: Cauchy + Woodbury via tf32 MMA (incl. exact k=L/2 fix)
    dim3 gridA(SEQ_L / 1024, D_MODEL);   // 8 x 256
    cauchy_mma<<<gridA, 256>>>(Lam_re, Lam_im, P_re, P_im, B_re, B_im, log_dt);

    // Stage 2: Hermitian fold + radix-8 half-length iFFT per row -> K
    // (also zeroes the D-tail of the output; no separate memset node)
    long kElems = (long)D_MODEL * SEQ_L;
    int tail = (int)((long)out_size > kElems ? (long)out_size - kElems : 0);
    cudaFuncSetAttribute(ifft_kernel,
                         cudaFuncAttributeMaxDynamicSharedMemorySize, 65536);
    ifft_kernel<<<D_MODEL, 512, 65536>>>(out, tail);
}

// round 17
// speedup vs baseline: 1.1183x; 1.0127x over previous
#include <cuda_runtime.h>
#include <math.h>
#include <stdint.h>

#define D_MODEL 256
#define STATE_N 64
#define SEQ_L   8192
#define HALF_L  4096

// Scratch: K_hat[d, L] complex64 (16 MB) as a device global (no runtime alloc).
__device__ float2 g_Khat[D_MODEL * SEQ_L];

// ---------------------------------------------------------------------------
// tf32 mma (operands: raw f32 bits; HW ignores low 13 mantissa bits = trunc)
// ---------------------------------------------------------------------------
__device__ __forceinline__ void mma_tf32(float& d0, float& d1, float& d2, float& d3,
                                         float a0, float a1, float a2, float a3,
                                         float b0, float b1)
{
    asm volatile(
        "mma.sync.aligned.m16n8k8.row.col.f32.tf32.tf32.f32 "
        "{%0,%1,%2,%3}, {%4,%5,%6,%7}, {%8,%9}, {%0,%1,%2,%3};"
        : "+f"(d0), "+f"(d1), "+f"(d2), "+f"(d3)
        : "r"(__float_as_uint(a0)), "r"(__float_as_uint(a1)),
          "r"(__float_as_uint(a2)), "r"(__float_as_uint(a3)),
          "r"(__float_as_uint(b0)), "r"(__float_as_uint(b1)));
}

__device__ __forceinline__ uint32_t tf32_rna(float x) {
    uint32_t u;
    asm("cvt.rna.tf32.f32 %0, %1;" : "=r"(u) : "f"(x));
    return u;
}

// ---------------------------------------------------------------------------
// Woodbury tail from the 8 fast-path sums (g purely imaginary form).
// ---------------------------------------------------------------------------
__device__ __forceinline__ float2 wb_fast(float SA, float SB, float SC, float SD,
                                          float TA, float TB, float TC, float TD,
                                          float pfr, float pfi)
{
    float PRBr = SA + TB, PRBi = SB - TA;
    float BRPr = SA - TB, BRPi = -SB - TA;
    float qr = 1.0f + SC, qi = -TC;
    float BRBr = SD, BRBi = -TD;
    float iq = 1.0f / (qr * qr + qi * qi);
    float numr = BRPr * PRBr - BRPi * PRBi;
    float numi = BRPr * PRBi + BRPi * PRBr;
    float tr = (numr * qr + numi * qi) * iq;
    float ti = (numi * qr - numr * qi) * iq;
    float hr = BRBr - tr, hi = BRBi - ti;
    return make_float2(pfr * hr - pfi * hi, pfr * hi + pfi * hr);
}

__device__ __forceinline__ float2 cmul(float2 a, float2 b) {
    return make_float2(a.x * b.x - a.y * b.y, a.x * b.y + a.y * b.x);
}

// ---------------------------------------------------------------------------
// Kernel 1: Cauchy + Woodbury via tf32 mma.sync.
// R17: geometry computed inline in the prologue (geom_init node removed).
// ---------------------------------------------------------------------------
__global__ void __launch_bounds__(256, 5) cauchy_mma(
    const float* __restrict__ Lam_re, const float* __restrict__ Lam_im,
    const float* __restrict__ P_re,   const float* __restrict__ P_im,
    const float* __restrict__ B_re,   const float* __restrict__ B_im,
    const float* __restrict__ log_dt)
{
    __shared__ float2 s_lisp[STATE_N];       // (lam_im, sp*sp) [init temp]
    __shared__ float  s_Sw[4 * STATE_N];     // tf32-rna S-weights [init temp]
    __shared__ float  s_Tw[4 * STATE_N];     // tf32-rna T-weights [init temp]
    __shared__ float4 s_lam4[32];            // [ch*4+qr] = (liA, sp2A, liB, sp2B)
    __shared__ float4 s_bf4[256];            // [(j*8+ch)*4+qr] = (S0,S1,T0,T1)
    __shared__ float  s_gi[1024];
    __shared__ float  s_pfr[1024], s_pfi[1024];
    __shared__ float  s_sums[8][8][36];      // [warp][sum-col][kloc 0..31 +pad]
    __shared__ float  s_scal_sh;

    const int d    = blockIdx.y;
    const int seg  = blockIdx.x;
    const int tid  = threadIdx.x;
    const int lane = tid & 31;
    const int warp = tid >> 5;

    if (tid < STATE_N) {
        const int idx = d * STATE_N + tid;
        float lr = Lam_re[idx];
        float li = Lam_im[idx];
        float sp = fmaxf(lr, 0.0f) + log1pf(expf(-fabsf(lr)));  // softplus
        float pr = P_re[idx], pi = P_im[idx];
        float br = B_re[idx], bi = B_im[idx];
        float w1r = pr * br + pi * bi;    // conj(P)*B
        float w1i = pr * bi - pi * br;
        float pp  = pr * pr + pi * pi;
        float bb  = br * br + bi * bi;
        s_lisp[tid] = make_float2(li, sp * sp);
        s_Sw[0 * STATE_N + tid] = __uint_as_float(tf32_rna(w1r * sp));
        s_Sw[1 * STATE_N + tid] = __uint_as_float(tf32_rna(w1i * sp));
        s_Sw[2 * STATE_N + tid] = __uint_as_float(tf32_rna(pp * sp));
        s_Sw[3 * STATE_N + tid] = __uint_as_float(tf32_rna(bb * sp));
        s_Tw[0 * STATE_N + tid] = __uint_as_float(tf32_rna(w1r));
        s_Tw[1 * STATE_N + tid] = __uint_as_float(tf32_rna(w1i));
        s_Tw[2 * STATE_N + tid] = __uint_as_float(tf32_rna(pp));
        s_Tw[3 * STATE_N + tid] = __uint_as_float(tf32_rna(bb));
    }
    if (tid == 0) s_scal_sh = 2.0f * expf(-log_dt[d]);
    __syncthreads();

    // Pack per-chunk constants into float4 tables.
    if (tid < 32) {
        int ch = tid >> 2, q = tid & 3;
        int n0 = ch * 8 + q, n1 = n0 + 4;
        float2 a = s_lisp[n0];
        float2 b = s_lisp[n1];
        s_lam4[tid] = make_float4(a.x, a.y, b.x, b.y);
    }
    {
        int t = tid;                      // 256 entries: j(8) x ch(8) x qr(4)
        int jj = t >> 5, ch = (t >> 2) & 7, q = t & 3;
        int n0 = ch * 8 + q, n1 = n0 + 4;
        float4 v;
        if (jj < 4) v = make_float4(s_Sw[jj * STATE_N + n0],
                                    s_Sw[jj * STATE_N + n1], 0.f, 0.f);
        else        v = make_float4(0.f, 0.f,
                                    s_Tw[(jj - 4) * STATE_N + n0],
                                    s_Tw[(jj - 4) * STATE_N + n1]);
        s_bf4[t] = v;
    }

    // per-k prologue: inline geometry (f32 arithmetic matching the reference)
    const float scal = s_scal_sh;
    const float w0 = (float)(-6.283185307179586476925286766559 / (double)SEQ_L);
    for (int kk = tid; kk < 1024; kk += 256) {
        int k = seg * 1024 + kk;
        float zs, zc;
        sincosf(w0 * (float)k, &zs, &zc);
        float dzr = 1.0f + zc, dzi = zs;
        if (k == HALF_L) { dzr = 1.1920929e-7f; dzi = 0.0f; }
        float idm = 1.0f / (dzr * dzr + dzi * dzi);
        float nr = 1.0f - zc, ni = -zs;
        s_gi[kk]  = scal * ((ni * dzr - nr * dzi) * idm);
        s_pfr[kk] = 2.0f * dzr * idm;
        s_pfi[kk] = -2.0f * dzi * idm;
    }
    __syncthreads();

    const int j  = lane >> 2;       // B-fragment column 0..7
    const int qr = lane & 3;
    float* swp = &s_sums[warp][0][0];

    for (int tp = 0; tp < 4; tp++) {
#pragma unroll
        for (int half = 0; half < 2; half++) {
            const int t = tp * 2 + half;
            const int base = (warp * 8 + t) * 16;
            const float gi0 = s_gi[base + (lane >> 2)];       // row l/4
            const float gi1 = s_gi[base + 8 + (lane >> 2)];   // row 8 + l/4

            float dS0 = 0.f, dS1 = 0.f, dS2 = 0.f, dS3 = 0.f;
            float dT0 = 0.f, dT1 = 0.f, dT2 = 0.f, dT3 = 0.f;

#pragma unroll
            for (int ch = 0; ch < 8; ch++) {
                float4 lam = s_lam4[ch * 4 + qr];
                float4 bf  = s_bf4[(j * 8 + ch) * 4 + qr];

                float di0 = gi0 - lam.x;
                float di1 = gi1 - lam.x;
                float di2 = gi0 - lam.z;
                float di3 = gi1 - lam.z;
                float m0 = fmaf(di0, di0, lam.y);
                float m1 = fmaf(di1, di1, lam.y);
                float m2 = fmaf(di2, di2, lam.w);
                float m3 = fmaf(di3, di3, lam.w);
                float p01, p23;
                float q01 = m0 * m1, q23 = m2 * m3;
                asm("rcp.approx.f32 %0, %1;" : "=f"(p01) : "f"(q01));
                asm("rcp.approx.f32 %0, %1;" : "=f"(p23) : "f"(q23));
                float i0 = p01 * m1, i1 = p01 * m0;
                float i2 = p23 * m3, i3 = p23 * m2;
                float r0 = di0 * i0, r1 = di1 * i1;
                float r2 = di2 * i2, r3 = di3 * i3;

                mma_tf32(dS0, dS1, dS2, dS3, i0, i1, i2, i3, bf.x, bf.y);
                mma_tf32(dT0, dT1, dT2, dT3, r0, r1, r2, r3, bf.z, bf.w);
            }

            float d0 = dS0 + dT0, d1 = dS1 + dT1;
            float d2 = dS2 + dT2, d3 = dS3 + dT3;

            // stage into [col][kloc] (pad 36): conflict-free STS/LDS
            int kl0 = half * 16 + (lane >> 2);
            swp[(2 * qr)     * 36 + kl0]     = d0;
            swp[(2 * qr + 1) * 36 + kl0]     = d1;
            swp[(2 * qr)     * 36 + kl0 + 8] = d2;
            swp[(2 * qr + 1) * 36 + kl0 + 8] = d3;
        }

        __syncwarp();
        // full-warp Woodbury over the pair's 32 k-points
        {
            int kloc = lane;
            float SA = swp[0 * 36 + kloc];
            float SB = swp[1 * 36 + kloc];
            float SC = swp[2 * 36 + kloc];
            float SD = swp[3 * 36 + kloc];
            float TA = swp[4 * 36 + kloc];
            float TB = swp[5 * 36 + kloc];
            float TC = swp[6 * 36 + kloc];
            float TD = swp[7 * 36 + kloc];
            int kk = warp * 128 + tp * 32 + lane;
            float2 r = wb_fast(SA, SB, SC, SD, TA, TB, TC, TD,
                               s_pfr[kk], s_pfi[kk]);
            g_Khat[d * SEQ_L + seg * 1024 + kk] = r;
        }
        __syncwarp();
    }

    // ---- exact fix of the eps-clamped point k = L/2 (tid 0 of seg 4 wrote
    // it above; same thread overwrites in program order) ----
    if (seg == 4 && tid == 0) {
        float zs, zc;
        sincosf(w0 * (float)HALF_L, &zs, &zc);
        float dzr = 1.1920929e-7f, dzi = 0.0f;
        float idm = 1.0f / (dzr * dzr + dzi * dzi);
        float nr = 1.0f - zc, ni = -zs;
        float gr = scal * (nr * dzr + ni * dzi) * idm;
        float gi = scal * (ni * dzr - nr * dzi) * idm;
        float pfr = 2.0f * dzr * idm, pfi = -2.0f * dzi * idm;

        float PRBr=0,PRBi=0,BRPr=0,BRPi=0,PRPr=0,PRPi=0,BRBr=0,BRBi=0;
        for (int n = 0; n < STATE_N; n++) {
            const int idx = d * STATE_N + n;
            float lr = Lam_re[idx];
            float li = Lam_im[idx];
            float sp = fmaxf(lr, 0.0f) + log1pf(expf(-fabsf(lr)));
            float pr = P_re[idx], pi = P_im[idx];
            float br = B_re[idx], bi = B_im[idx];
            float w1r = pr * br + pi * bi;
            float w1i = pr * bi - pi * br;
            float pp  = pr * pr + pi * pi;
            float bb  = br * br + bi * bi;
            float dr = gr + sp;
            float di = gi - li;
            float m  = fmaf(dr, dr, di * di);
            float inv = 1.0f / m;
            float Rtr = dr * inv;
            float Rti = -di * inv;
            PRBr += w1r * Rtr - w1i * Rti;
            PRBi += w1r * Rti + w1i * Rtr;
            BRPr += w1r * Rtr + w1i * Rti;
            BRPi += w1r * Rti - w1i * Rtr;
            PRPr += pp * Rtr;  PRPi += pp * Rti;
            BRBr += bb * Rtr;  BRBi += bb * Rti;
        }
        float qr2 = 1.0f + PRPr, qi2 = PRPi;
        float iq = 1.0f / (qr2 * qr2 + qi2 * qi2);
        float numr = BRPr * PRBr - BRPi * PRBi;
        float numi = BRPr * PRBi + BRPi * PRBr;
        float tr = (numr * qr2 + numi * qi2) * iq;
        float ti = (numi * qr2 - numr * qi2) * iq;
        float hr = BRBr - tr, hi = BRBi - ti;
        g_Khat[d * SEQ_L + HALF_L] = make_float2(pfr * hr - pfi * hi,
                                                 pfr * hi + pfi * hr);
    }
}

// ---------------------------------------------------------------------------
// Kernel 2: Re(ifft_L(X)) = Hermitian fold + 4096-pt RADIX-8 inverse Stockham
// (4 stages). 512 threads = 1 butterfly/thread/stage. Also zeroes the D-tail.
// ---------------------------------------------------------------------------
__global__ void __launch_bounds__(512) ifft_kernel(float* __restrict__ out,
                                                   int tail)
{
    extern __shared__ float2 sm[];
    float2* x = sm;
    float2* y = sm + HALF_L;

    const int d   = blockIdx.x;
    const int tid = threadIdx.x;
    const int NT  = 512;
    const float C = 0.70710678118654752440f;   // sqrt(2)/2

    const float2* src = g_Khat + d * SEQ_L;

    // Fold the output tail zeroing into block 0 (replaces cudaMemsetAsync).
    if (d == 0 && tid < tail)
        out[D_MODEL * SEQ_L + tid] = 0.0f;

    // Hermitian fold + even/odd pack:  x[k] = E[k] + i*O[k]
    const float thL = 6.28318530717958647692f / (float)SEQ_L;
    for (int kk = tid; kk < HALF_L; kk += NT) {
        float2 Xa  = src[kk];
        float2 Xam = src[kk == 0 ? 0 : SEQ_L - kk];
        float2 Xb  = src[kk + HALF_L];
        float2 Xbm = src[HALF_L - kk];
        float Ar = 0.5f * (Xa.x + Xam.x), Ai = 0.5f * (Xa.y - Xam.y);
        float Br = 0.5f * (Xb.x + Xbm.x), Bi = 0.5f * (Xb.y - Xbm.y);
        float Er = 0.5f * (Ar + Br), Ei = 0.5f * (Ai + Bi);
        float Dr = 0.5f * (Ar - Br), Di = 0.5f * (Ai - Bi);
        float swr, swi;
        __sincosf(thL * (float)kk, &swi, &swr);
        float Or = Dr * swr - Di * swi;
        float Oi = Dr * swi + Di * swr;
        x[kk] = make_float2(Er - Oi, Ei + Or);
    }
    __syncthreads();

    // 4 radix-8 inverse Stockham stages (4096 = 8^4), e^{+} twiddles
    int n = HALF_L, s = 1, ls = 0;
    while (n > 1) {
        const int m = n >> 3;
        const float th = 6.28318530717958647692f / (float)n;
        {
            const int u = tid;              // exactly 512 butterflies
            int p = u >> ls;
            int q = u & (s - 1);
            int base = q + s * p;
            int st = s * m;
            float2 t0 = x[base];
            float2 t1 = x[base + st];
            float2 t2 = x[base + 2 * st];
            float2 t3 = x[base + 3 * st];
            float2 t4 = x[base + 4 * st];
            float2 t5 = x[base + 5 * st];
            float2 t6 = x[base + 6 * st];
            float2 t7 = x[base + 7 * st];

            float2 u0 = make_float2(t0.x + t4.x, t0.y + t4.y);
            float2 u1 = make_float2(t1.x + t5.x, t1.y + t5.y);
            float2 u2 = make_float2(t2.x + t6.x, t2.y + t6.y);
            float2 u3 = make_float2(t3.x + t7.x, t3.y + t7.y);
            float2 v0 = make_float2(t0.x - t4.x, t0.y - t4.y);
            float2 v1 = make_float2(t1.x - t5.x, t1.y - t5.y);
            float2 v2 = make_float2(t2.x - t6.x, t2.y - t6.y);
            float2 v3 = make_float2(t3.x - t7.x, t3.y - t7.y);

            // v twiddles: e^{+i pi t/4}, t = 1,2,3
            float2 v1p = make_float2(C * (v1.x - v1.y), C * (v1.x + v1.y));
            float2 v2p = make_float2(-v2.y, v2.x);
            float2 v3p = make_float2(-C * (v3.x + v3.y), C * (v3.x - v3.y));

            // DFT4+ on u -> X0, X2, X4, X6
            float2 e0 = make_float2(u0.x + u2.x, u0.y + u2.y);
            float2 e1 = make_float2(u0.x - u2.x, u0.y - u2.y);
            float2 o0 = make_float2(u1.x + u3.x, u1.y + u3.y);
            float2 o1 = make_float2(u1.x - u3.x, u1.y - u3.y);
            float2 X0 = make_float2(e0.x + o0.x, e0.y + o0.y);
            float2 X4 = make_float2(e0.x - o0.x, e0.y - o0.y);
            float2 X2 = make_float2(e1.x - o1.y, e1.y + o1.x);
            float2 X6 = make_float2(e1.x + o1.y, e1.y - o1.x);

            // DFT4+ on v' -> X1, X3, X5, X7
            float2 f0 = make_float2(v0.x + v2p.x, v0.y + v2p.y);
            float2 f1 = make_float2(v0.x - v2p.x, v0.y - v2p.y);
            float2 g0 = make_float2(v1p.x + v3p.x, v1p.y + v3p.y);
            float2 g1 = make_float2(v1p.x - v3p.x, v1p.y - v3p.y);
            float2 X1 = make_float2(f0.x + g0.x, f0.y + g0.y);
            float2 X5 = make_float2(f0.x - g0.x, f0.y - g0.y);
            float2 X3 = make_float2(f1.x - g1.y, f1.y + g1.x);
            float2 X7 = make_float2(f1.x + g1.y, f1.y - g1.x);

            // output twiddles w^t, w = e^{+i th p}
            float w1i, w1r;
            __sincosf(th * (float)p, &w1i, &w1r);
            float2 w1 = make_float2(w1r, w1i);
            float2 w2 = cmul(w1, w1);
            float2 w3 = cmul(w2, w1);
            float2 w4 = cmul(w2, w2);
            float2 w5 = cmul(w3, w2);
            float2 w6 = cmul(w3, w3);
            float2 w7 = cmul(w4, w3);

            int ob = q + s * 8 * p;
            y[ob]         = X0;
            y[ob + s]     = cmul(X1, w1);
            y[ob + 2 * s] = cmul(X2, w2);
            y[ob + 3 * s] = cmul(X3, w3);
            y[ob + 4 * s] = cmul(X4, w4);
            y[ob + 5 * s] = cmul(X5, w5);
            y[ob + 6 * s] = cmul(X6, w6);
            y[ob + 7 * s] = cmul(X7, w7);
        }
        __syncthreads();
        float2* tmp = x; x = y; y = tmp;
        n = m; s <<= 3; ls += 3;
    }

    // x[m] = K[2m] + i*K[2m+1]  ->  interleaved real output
    const float scale = 1.0f / (float)HALF_L;
    float* dstp = out + d * SEQ_L;
    for (int mI = tid; mI < HALF_L; mI += NT) {
        float2 v = x[mI];
        dstp[2 * mI]     = v.x * scale;
        dstp[2 * mI + 1] = v.y * scale;
    }
}

// ---------------------------------------------------------------------------
extern "C" void kernel_launch(void* const* d_in, const int* in_sizes, int n_in,
                              void* d_out, int out_size)
{
    const float* Lam_re = (const float*)d_in[0];
    const float* Lam_im = (const float*)d_in[1];
    const float* P_re   = (const float*)d_in[2];
    const float* P_im   = (const float*)d_in[3];
    const float* B_re   = (const float*)d_in[4];
    const float* B_im   = (const float*)d_in[5];
    const float* log_dt = (const float*)d_in[6];

    float* out = (float*)d_out;

    // Stage 1: Cauchy + Woodbury via tf32 MMA (incl. exact k=L/2 fix)
    dim3 gridA(SEQ_L / 1024, D_MODEL);   // 8 x 256
    cauchy_mma<<<gridA, 256>>>(Lam_re, Lam_im, P_re, P_im, B_re, B_im, log_dt);

    // Stage 2: Hermitian fold + radix-8 half-length iFFT per row -> K
    // (also zeroes the D-tail of the output; no separate memset node)
    long kElems = (long)D_MODEL * SEQ_L;
    int tail = (int)((long)out_size > kElems ? (long)out_size - kElems : 0);
    cudaFuncSetAttribute(ifft_kernel,
                         cudaFuncAttributeMaxDynamicSharedMemorySize, 65536);
    ifft_kernel<<<D_MODEL, 512, 65536>>>(out, tail);
}